// round 6
// baseline (speedup 1.0000x reference)
#include <cuda_runtime.h>
#include <cuda_bf16.h>
#include <cstddef>

// ---------------------------------------------------------------------------
// InfiniAttention: B=8, T=1024, C=768, H=12, D=64, MEM=64
//   qkv   = x @ w_qkv + b_qkv                         [8192, 2304]
//   memp  = memory @ w_mem + b_mem                    [64, 768]
//   attn  = softmax(QK^T/8)V + softmax(Q Mk^T/8)Mk    [8192, 768] (head-interleaved)
//   out   = attn @ w_out + b_out                      [8192, 768]
// ---------------------------------------------------------------------------

#define BATCH 8
#define SEQ   1024
#define EMB   768
#define HEADS 12
#define HDIM  64
#define MEMSZ 64
#define NTOK  (BATCH * SEQ)       // 8192
#define QKVW  (3 * EMB)           // 2304

// Scratch (device globals; no runtime allocation allowed)
__device__ float g_qkv[NTOK * QKVW];     // 75.5 MB
__device__ float g_attn[NTOK * EMB];     // 25.2 MB
__device__ float g_memproj[MEMSZ * EMB]; // 192 KB

// ---------------------------------------------------------------------------
// Generic SGEMM + bias: C[M,N] = A[M,K] @ B[K,N] + bias[N]
// 128x128 tile, BK=16, 256 threads, 8x8 per thread (4+4 split fragments).
// Requires: N % 128 == 0, K % 16 == 0 (M guarded).
// ---------------------------------------------------------------------------
__global__ __launch_bounds__(256) void sgemm_bias_kernel(
    const float* __restrict__ A, const float* __restrict__ B,
    const float* __restrict__ bias, float* __restrict__ C,
    int M, int N, int K)
{
    __shared__ float As[16][128];   // [k][m]
    __shared__ float Bs[16][128];   // [k][n]

    const int tid  = threadIdx.x;
    const int tx   = tid & 15;
    const int ty   = tid >> 4;
    const int row0 = blockIdx.y * 128;
    const int col0 = blockIdx.x * 128;

    float acc[8][8];
#pragma unroll
    for (int i = 0; i < 8; i++)
#pragma unroll
        for (int j = 0; j < 8; j++) acc[i][j] = 0.f;

    for (int k0 = 0; k0 < K; k0 += 16) {
        // load A tile (128 x 16), store transposed into As[k][m]
#pragma unroll
        for (int i = 0; i < 2; i++) {
            int f  = tid + i * 256;       // float4 index 0..511
            int r  = f >> 2;              // row in tile 0..127
            int c4 = (f & 3) << 2;        // k offset 0,4,8,12
            int gr = row0 + r;
            float4 va = make_float4(0.f, 0.f, 0.f, 0.f);
            if (gr < M)
                va = *reinterpret_cast<const float4*>(&A[(size_t)gr * K + k0 + c4]);
            As[c4 + 0][r] = va.x;
            As[c4 + 1][r] = va.y;
            As[c4 + 2][r] = va.z;
            As[c4 + 3][r] = va.w;
        }
        // load B tile (16 x 128) directly
#pragma unroll
        for (int i = 0; i < 2; i++) {
            int f  = tid + i * 256;
            int r  = f >> 5;              // 0..15
            int c4 = (f & 31) << 2;       // 0..124
            *reinterpret_cast<float4*>(&Bs[r][c4]) =
                *reinterpret_cast<const float4*>(&B[(size_t)(k0 + r) * N + col0 + c4]);
        }
        __syncthreads();

#pragma unroll
        for (int kk = 0; kk < 16; kk++) {
            // split fragments: rows {4ty..4ty+3, 64+4ty..}, cols {4tx.., 64+4tx..}
            float4 a0 = *reinterpret_cast<const float4*>(&As[kk][ty * 4]);
            float4 a1 = *reinterpret_cast<const float4*>(&As[kk][ty * 4 + 64]);
            float4 b0 = *reinterpret_cast<const float4*>(&Bs[kk][tx * 4]);
            float4 b1 = *reinterpret_cast<const float4*>(&Bs[kk][tx * 4 + 64]);
            float av[8] = {a0.x, a0.y, a0.z, a0.w, a1.x, a1.y, a1.z, a1.w};
            float bv[8] = {b0.x, b0.y, b0.z, b0.w, b1.x, b1.y, b1.z, b1.w};
#pragma unroll
            for (int i = 0; i < 8; i++)
#pragma unroll
                for (int j = 0; j < 8; j++)
                    acc[i][j] = fmaf(av[i], bv[j], acc[i][j]);
        }
        __syncthreads();
    }

    // epilogue with bias
#pragma unroll
    for (int ih = 0; ih < 2; ih++) {
#pragma unroll
        for (int i = 0; i < 4; i++) {
            int gr = row0 + ih * 64 + ty * 4 + i;
            if (gr < M) {
#pragma unroll
                for (int jh = 0; jh < 2; jh++) {
                    int gc = col0 + jh * 64 + tx * 4;
                    float4 bz = *reinterpret_cast<const float4*>(&bias[gc]);
                    int ii = ih * 4 + i;
                    int jj = jh * 4;
                    float4 r = make_float4(acc[ii][jj + 0] + bz.x,
                                           acc[ii][jj + 1] + bz.y,
                                           acc[ii][jj + 2] + bz.z,
                                           acc[ii][jj + 3] + bz.w);
                    *reinterpret_cast<float4*>(&C[(size_t)gr * N + gc]) = r;
                }
            }
        }
    }
}

// ---------------------------------------------------------------------------
// Fused flash-style attention for one (b,h) head and a 64-query tile.
// Pass 0: 16 local key tiles of 64 with online softmax.
// Pass 1: 64 memory keys (projected memory as both K and V), separate softmax.
// Output = normalized local O + normalized memory O, written head-interleaved.
//
// Shared layout (48 KB exactly):
//   q_sT : [d][row] transposed, XOR-swizzled (col ^ (d & 60))
//   kp_s : K transposed+swizzled during S, reused for P [row][key] during PV
//   v_s  : V natural [key][d]
// ---------------------------------------------------------------------------
__global__ __launch_bounds__(256) void attn_kernel(
    const float* __restrict__ qkv, const float* __restrict__ memproj,
    float* __restrict__ attn)
{
    __shared__ float q_sT[64 * 64];
    __shared__ float kp_s[64 * 64];
    __shared__ float v_s [64 * 64];

    const int tid = threadIdx.x;
    const int tx  = tid & 15;            // key/d column group
    const int ty  = tid >> 4;            // query row group
    const int bh  = blockIdx.y;
    const int b   = bh / HEADS;
    const int h   = bh % HEADS;
    const int q0  = blockIdx.x * 64;

    // ---- load Q tile, transposed + swizzled ----
#pragma unroll
    for (int i = 0; i < 4; i++) {
        int f  = tid + i * 256;
        int r  = f >> 4;                 // row 0..63
        int d4 = (f & 15) << 2;          // d 0..60 step 4
        float4 qv = *reinterpret_cast<const float4*>(
            &qkv[(size_t)(b * SEQ + q0 + r) * QKVW + h * HDIM + d4]);
        int c = r ^ d4;                  // swizzle: (d&60)==d4 for all 4 lanes of the vec
        q_sT[(d4 + 0) * 64 + c] = qv.x;
        q_sT[(d4 + 1) * 64 + c] = qv.y;
        q_sT[(d4 + 2) * 64 + c] = qv.z;
        q_sT[(d4 + 3) * 64 + c] = qv.w;
    }

    float o[4][4], ofin[4][4], m_r[4], l_r[4];
#pragma unroll
    for (int i = 0; i < 4; i++) {
        m_r[i] = -1e30f; l_r[i] = 0.f;
#pragma unroll
        for (int j = 0; j < 4; j++) { o[i][j] = 0.f; ofin[i][j] = 0.f; }
    }

    for (int pass = 0; pass < 2; pass++) {
        const int ntiles = (pass == 0) ? (SEQ / 64) : 1;
        for (int kt = 0; kt < ntiles; kt++) {
            __syncthreads();  // protect kp_s / v_s reuse across iterations

            // ---- load K (transposed+swizzled) and V (natural) ----
#pragma unroll
            for (int i = 0; i < 4; i++) {
                int f  = tid + i * 256;
                int r  = f >> 4;
                int d4 = (f & 15) << 2;
                float4 kv, vv;
                if (pass == 0) {
                    size_t base = (size_t)(b * SEQ + kt * 64 + r) * QKVW + h * HDIM + d4;
                    kv = *reinterpret_cast<const float4*>(&qkv[base + EMB]);
                    vv = *reinterpret_cast<const float4*>(&qkv[base + 2 * EMB]);
                } else {
                    size_t base = (size_t)r * EMB + h * HDIM + d4;
                    kv = *reinterpret_cast<const float4*>(&memproj[base]);
                    vv = kv;  // memory serves as both K and V
                }
                int c = r ^ d4;
                kp_s[(d4 + 0) * 64 + c] = kv.x;
                kp_s[(d4 + 1) * 64 + c] = kv.y;
                kp_s[(d4 + 2) * 64 + c] = kv.z;
                kp_s[(d4 + 3) * 64 + c] = kv.w;
                *reinterpret_cast<float4*>(&v_s[r * 64 + d4]) = vv;
            }
            __syncthreads();

            // ---- S = Q K^T (outer product over d) ----
            float s[4][4];
#pragma unroll
            for (int i = 0; i < 4; i++)
#pragma unroll
                for (int j = 0; j < 4; j++) s[i][j] = 0.f;

#pragma unroll 16
            for (int d = 0; d < 64; d++) {
                int xr = d & 60;
                float4 a  = *reinterpret_cast<const float4*>(&q_sT[d * 64 + ((ty << 2) ^ xr)]);
                float4 bb = *reinterpret_cast<const float4*>(&kp_s[d * 64 + ((tx << 2) ^ xr)]);
                float av[4] = {a.x, a.y, a.z, a.w};
                float bv[4] = {bb.x, bb.y, bb.z, bb.w};
#pragma unroll
                for (int i = 0; i < 4; i++)
#pragma unroll
                    for (int j = 0; j < 4; j++)
                        s[i][j] = fmaf(av[i], bv[j], s[i][j]);
            }

            // ---- online softmax update (scale = 1/sqrt(64) = 0.125) ----
#pragma unroll
            for (int i = 0; i < 4; i++) {
                float rm = -1e30f;
#pragma unroll
                for (int j = 0; j < 4; j++) {
                    s[i][j] *= 0.125f;
                    rm = fmaxf(rm, s[i][j]);
                }
#pragma unroll
                for (int off = 1; off < 16; off <<= 1)
                    rm = fmaxf(rm, __shfl_xor_sync(0xffffffffu, rm, off));
                float mnew = fmaxf(m_r[i], rm);
                float fac  = __expf(m_r[i] - mnew);
                float rs   = 0.f;
#pragma unroll
                for (int j = 0; j < 4; j++) {
                    s[i][j] = __expf(s[i][j] - mnew);
                    rs += s[i][j];
                }
#pragma unroll
                for (int off = 1; off < 16; off <<= 1)
                    rs += __shfl_xor_sync(0xffffffffu, rs, off);
                l_r[i] = l_r[i] * fac + rs;
                m_r[i] = mnew;
#pragma unroll
                for (int j = 0; j < 4; j++) o[i][j] *= fac;
            }

            __syncthreads();  // all K reads done before overwriting kp_s with P

            // ---- stash P in kp_s, natural [row][key] layout ----
#pragma unroll
            for (int i = 0; i < 4; i++) {
                float4 pv = make_float4(s[i][0], s[i][1], s[i][2], s[i][3]);
                *reinterpret_cast<float4*>(&kp_s[((ty << 2) + i) * 64 + (tx << 2)]) = pv;
            }
            __syncthreads();

            // ---- O += P V ----
#pragma unroll 16
            for (int kk = 0; kk < 64; kk++) {
                float4 bb = *reinterpret_cast<const float4*>(&v_s[kk * 64 + (tx << 2)]);
                float bv[4] = {bb.x, bb.y, bb.z, bb.w};
#pragma unroll
                for (int i = 0; i < 4; i++) {
                    float a = kp_s[((ty << 2) + i) * 64 + kk];  // broadcast read
#pragma unroll
                    for (int j = 0; j < 4; j++)
                        o[i][j] = fmaf(a, bv[j], o[i][j]);
                }
            }
        }

        // ---- finalize this pass: accumulate normalized O, reset stats ----
#pragma unroll
        for (int i = 0; i < 4; i++) {
            float inv = 1.0f / l_r[i];
#pragma unroll
            for (int j = 0; j < 4; j++) {
                ofin[i][j] += o[i][j] * inv;
                o[i][j] = 0.f;
            }
            m_r[i] = -1e30f;
            l_r[i] = 0.f;
        }
    }

    // ---- write out, head-interleaved [b,t,h*64+d] ----
#pragma unroll
    for (int i = 0; i < 4; i++) {
        size_t idx = (size_t)(b * SEQ + q0 + (ty << 2) + i) * EMB + h * HDIM + (tx << 2);
        *reinterpret_cast<float4*>(&attn[idx]) =
            make_float4(ofin[i][0], ofin[i][1], ofin[i][2], ofin[i][3]);
    }
}

// ---------------------------------------------------------------------------
// Launch
// ---------------------------------------------------------------------------
extern "C" void kernel_launch(void* const* d_in, const int* in_sizes, int n_in,
                              void* d_out, int out_size)
{
    const float* x      = (const float*)d_in[0];
    const float* w_qkv  = (const float*)d_in[1];
    const float* b_qkv  = (const float*)d_in[2];
    const float* w_out  = (const float*)d_in[3];
    const float* b_out  = (const float*)d_in[4];
    const float* w_mem  = (const float*)d_in[5];
    const float* b_mem  = (const float*)d_in[6];
    const float* memory = (const float*)d_in[7];
    float* out = (float*)d_out;

    float *qkv, *attn, *memp;
    cudaGetSymbolAddress((void**)&qkv,  g_qkv);
    cudaGetSymbolAddress((void**)&attn, g_attn);
    cudaGetSymbolAddress((void**)&memp, g_memproj);

    // 1) QKV projection: [8192,768] @ [768,2304] + b  -> g_qkv
    {
        dim3 grid(QKVW / 128, NTOK / 128);
        sgemm_bias_kernel<<<grid, 256>>>(x, w_qkv, b_qkv, qkv, NTOK, QKVW, EMB);
    }
    // 2) Memory projection: [64,768] @ [768,768] + b -> g_memproj
    {
        dim3 grid(EMB / 128, 1);
        sgemm_bias_kernel<<<grid, 256>>>(memory, w_mem, b_mem, memp, MEMSZ, EMB, EMB);
    }
    // 3) Fused local + memory attention -> g_attn
    {
        dim3 grid(SEQ / 64, BATCH * HEADS);
        attn_kernel<<<grid, 256>>>(qkv, memp, attn);
    }
    // 4) Output projection: [8192,768] @ [768,768] + b -> out
    {
        dim3 grid(EMB / 128, NTOK / 128);
        sgemm_bias_kernel<<<grid, 256>>>(attn, w_out, b_out, out, NTOK, EMB, EMB);
    }
}

// round 8
// speedup vs baseline: 2.5290x; 2.5290x over previous
#include <cuda_runtime.h>
#include <cuda_bf16.h>
#include <cstdint>
#include <cstddef>

// ---------------------------------------------------------------------------
// InfiniAttention: B=8, T=1024, C=768, H=12, D=64, MEM=64
// All heavy math on tf32 mma.sync (base compute_103 feature set — tcgen05 is
// sm_103a-suffix-only and this toolchain emits .target sm_103).
// ---------------------------------------------------------------------------

#define BATCH 8
#define SEQ   1024
#define EMB   768
#define HEADS 12
#define HDIM  64
#define MEMSZ 64
#define NTOK  (BATCH * SEQ)       // 8192
#define QKVW  (3 * EMB)           // 2304

// Scratch (device globals; no runtime allocation allowed)
__device__ float g_qkv[NTOK * QKVW];        // 75.5 MB
__device__ float g_attn[NTOK * EMB];        // 25.2 MB
__device__ float g_memproj[MEMSZ * EMB];    // 192 KB
__device__ float g_wqkvT[QKVW * EMB];       // 7.1 MB  (w_qkv^T -> [N,K])
__device__ float g_woutT[EMB * EMB];        // 2.25 MB (w_out^T -> [N,K])

// ===========================================================================
// tf32 warp MMA helpers (m16n8k8), standard sm_80 fragment layout:
//   A (row-major 16x8): a0=(gid,tg) a1=(gid+8,tg) a2=(gid,tg+4) a3=(gid+8,tg+4)
//   B (col-major 8x8):  b0=(k=tg,n=gid) b1=(k=tg+4,n=gid)
//   C/D:                c0=(gid,2tg) c1=(gid,2tg+1) c2=(gid+8,2tg) c3=(gid+8,2tg+1)
// where gid = lane>>2, tg = lane&3.
// ===========================================================================
__device__ __forceinline__ void mma_tf32(float d[4], const uint32_t a[4],
                                         const uint32_t b[2], const float c[4]) {
    asm volatile(
        "mma.sync.aligned.m16n8k8.row.col.f32.tf32.tf32.f32 "
        "{%0,%1,%2,%3}, {%4,%5,%6,%7}, {%8,%9}, {%10,%11,%12,%13};"
        : "=f"(d[0]), "=f"(d[1]), "=f"(d[2]), "=f"(d[3])
        : "r"(a[0]), "r"(a[1]), "r"(a[2]), "r"(a[3]),
          "r"(b[0]), "r"(b[1]),
          "f"(c[0]), "f"(c[1]), "f"(c[2]), "f"(c[3]));
}

__device__ __forceinline__ uint32_t f2tf32(float f) {
    uint32_t u;
    asm("cvt.rna.tf32.f32 %0, %1;" : "=r"(u) : "f"(f));
    return u;
}

// ===========================================================================
// Transpose: out[c][r] = in[r][c].  R, C multiples of 32. block (32,8).
// ===========================================================================
__global__ void transpose_kernel(const float* __restrict__ in, float* __restrict__ out,
                                 int R, int C)
{
    __shared__ float t[32][33];
    int c0 = blockIdx.x * 32, r0 = blockIdx.y * 32;
    int x = threadIdx.x, y = threadIdx.y;
#pragma unroll
    for (int i = 0; i < 32; i += 8)
        t[y + i][x] = in[(size_t)(r0 + y + i) * C + c0 + x];
    __syncthreads();
#pragma unroll
    for (int i = 0; i < 32; i += 8)
        out[(size_t)(c0 + y + i) * R + r0 + x] = t[x][y + i];
}

// ===========================================================================
// tf32 MMA GEMM + bias: C[M,N] = A[M,K] @ BT[N,K]^T + bias[N]
// 128x128x32 CTA tile, 256 threads (8 warps, 4x2 grid of 32x64 warp tiles).
// Smem rows stride 36 floats: fragment LDS conflict-free, float4 STS aligned.
// Requires M%128==0, N%128==0, K%32==0.
// ===========================================================================
__global__ __launch_bounds__(256) void gemm_mma_kernel(
    const float* __restrict__ A, const float* __restrict__ BT,
    const float* __restrict__ bias, float* __restrict__ C,
    int M, int N, int K)
{
    __shared__ __align__(16) float As[128 * 36];   // [m][k]
    __shared__ __align__(16) float Bs[128 * 36];   // [n][k]

    const int tid  = threadIdx.x;
    const int lane = tid & 31;
    const int warp = tid >> 5;
    const int gid  = lane >> 2;
    const int tg   = lane & 3;
    const int m0   = (warp & 3) * 32;
    const int n0   = (warp >> 2) * 64;
    const int row0 = blockIdx.y * 128;
    const int col0 = blockIdx.x * 128;

    float acc[2][8][4];
#pragma unroll
    for (int i = 0; i < 2; i++)
#pragma unroll
        for (int j = 0; j < 8; j++)
#pragma unroll
            for (int e = 0; e < 4; e++) acc[i][j][e] = 0.f;

    const int nkt = K / 32;
    float4 ra[4], rb[4];

    // prologue: stage tile 0
#pragma unroll
    for (int i = 0; i < 4; i++) {
        int f = tid + i * 256, m = f >> 3, k4 = f & 7;
        ra[i] = *reinterpret_cast<const float4*>(&A [(size_t)(row0 + m) * K + k4 * 4]);
        rb[i] = *reinterpret_cast<const float4*>(&BT[(size_t)(col0 + m) * K + k4 * 4]);
    }

    for (int kt = 0; kt < nkt; kt++) {
        // commit staged regs -> smem (tf32 convert)
#pragma unroll
        for (int i = 0; i < 4; i++) {
            int f = tid + i * 256, m = f >> 3, k4 = f & 7;
            uint4 ua = make_uint4(f2tf32(ra[i].x), f2tf32(ra[i].y),
                                  f2tf32(ra[i].z), f2tf32(ra[i].w));
            uint4 ub = make_uint4(f2tf32(rb[i].x), f2tf32(rb[i].y),
                                  f2tf32(rb[i].z), f2tf32(rb[i].w));
            *reinterpret_cast<uint4*>(&As[m * 36 + k4 * 4]) = ua;
            *reinterpret_cast<uint4*>(&Bs[m * 36 + k4 * 4]) = ub;
        }
        __syncthreads();

        // prefetch next tile while MMAs run
        if (kt + 1 < nkt) {
            int k0 = (kt + 1) * 32;
#pragma unroll
            for (int i = 0; i < 4; i++) {
                int f = tid + i * 256, m = f >> 3, k4 = f & 7;
                ra[i] = *reinterpret_cast<const float4*>(&A [(size_t)(row0 + m) * K + k0 + k4 * 4]);
                rb[i] = *reinterpret_cast<const float4*>(&BT[(size_t)(col0 + m) * K + k0 + k4 * 4]);
            }
        }

#pragma unroll
        for (int kc = 0; kc < 4; kc++) {
            const int kb = kc * 8;
            uint32_t af[2][4];
#pragma unroll
            for (int mf = 0; mf < 2; mf++) {
                int mr = m0 + mf * 16 + gid;
                af[mf][0] = __float_as_uint(As[mr * 36 + kb + tg]);
                af[mf][1] = __float_as_uint(As[(mr + 8) * 36 + kb + tg]);
                af[mf][2] = __float_as_uint(As[mr * 36 + kb + tg + 4]);
                af[mf][3] = __float_as_uint(As[(mr + 8) * 36 + kb + tg + 4]);
            }
#pragma unroll
            for (int nf = 0; nf < 8; nf++) {
                int nr = n0 + nf * 8 + gid;
                uint32_t bf[2];
                bf[0] = __float_as_uint(Bs[nr * 36 + kb + tg]);
                bf[1] = __float_as_uint(Bs[nr * 36 + kb + tg + 4]);
                mma_tf32(acc[0][nf], af[0], bf, acc[0][nf]);
                mma_tf32(acc[1][nf], af[1], bf, acc[1][nf]);
            }
        }
        __syncthreads();
    }

    // epilogue with bias
#pragma unroll
    for (int mf = 0; mf < 2; mf++) {
#pragma unroll
        for (int nf = 0; nf < 8; nf++) {
            int row = row0 + m0 + mf * 16 + gid;
            int col = col0 + n0 + nf * 8 + 2 * tg;
            float2 bz = *reinterpret_cast<const float2*>(&bias[col]);
            *reinterpret_cast<float2*>(&C[(size_t)row * N + col]) =
                make_float2(acc[mf][nf][0] + bz.x, acc[mf][nf][1] + bz.y);
            *reinterpret_cast<float2*>(&C[(size_t)(row + 8) * N + col]) =
                make_float2(acc[mf][nf][2] + bz.x, acc[mf][nf][3] + bz.y);
        }
    }
}

// ---------------------------------------------------------------------------
// SIMT SGEMM + bias (tiny memory projection only, M=64)
// ---------------------------------------------------------------------------
__global__ __launch_bounds__(256) void sgemm_bias_kernel(
    const float* __restrict__ A, const float* __restrict__ B,
    const float* __restrict__ bias, float* __restrict__ C,
    int M, int N, int K)
{
    __shared__ float As[16][128];
    __shared__ float Bs[16][128];

    const int tid  = threadIdx.x;
    const int tx   = tid & 15;
    const int ty   = tid >> 4;
    const int row0 = blockIdx.y * 128;
    const int col0 = blockIdx.x * 128;

    float acc[8][8];
#pragma unroll
    for (int i = 0; i < 8; i++)
#pragma unroll
        for (int j = 0; j < 8; j++) acc[i][j] = 0.f;

    for (int k0 = 0; k0 < K; k0 += 16) {
#pragma unroll
        for (int i = 0; i < 2; i++) {
            int f  = tid + i * 256;
            int r  = f >> 2;
            int c4 = (f & 3) << 2;
            int gr = row0 + r;
            float4 va = make_float4(0.f, 0.f, 0.f, 0.f);
            if (gr < M)
                va = *reinterpret_cast<const float4*>(&A[(size_t)gr * K + k0 + c4]);
            As[c4 + 0][r] = va.x;
            As[c4 + 1][r] = va.y;
            As[c4 + 2][r] = va.z;
            As[c4 + 3][r] = va.w;
        }
#pragma unroll
        for (int i = 0; i < 2; i++) {
            int f  = tid + i * 256;
            int r  = f >> 5;
            int c4 = (f & 31) << 2;
            *reinterpret_cast<float4*>(&Bs[r][c4]) =
                *reinterpret_cast<const float4*>(&B[(size_t)(k0 + r) * N + col0 + c4]);
        }
        __syncthreads();

#pragma unroll
        for (int kk = 0; kk < 16; kk++) {
            float4 a0 = *reinterpret_cast<const float4*>(&As[kk][ty * 4]);
            float4 a1 = *reinterpret_cast<const float4*>(&As[kk][ty * 4 + 64]);
            float4 b0 = *reinterpret_cast<const float4*>(&Bs[kk][tx * 4]);
            float4 b1 = *reinterpret_cast<const float4*>(&Bs[kk][tx * 4 + 64]);
            float av[8] = {a0.x, a0.y, a0.z, a0.w, a1.x, a1.y, a1.z, a1.w};
            float bv[8] = {b0.x, b0.y, b0.z, b0.w, b1.x, b1.y, b1.z, b1.w};
#pragma unroll
            for (int i = 0; i < 8; i++)
#pragma unroll
                for (int j = 0; j < 8; j++)
                    acc[i][j] = fmaf(av[i], bv[j], acc[i][j]);
        }
        __syncthreads();
    }

#pragma unroll
    for (int ih = 0; ih < 2; ih++) {
#pragma unroll
        for (int i = 0; i < 4; i++) {
            int gr = row0 + ih * 64 + ty * 4 + i;
            if (gr < M) {
#pragma unroll
                for (int jh = 0; jh < 2; jh++) {
                    int gc = col0 + jh * 64 + tx * 4;
                    float4 bz = *reinterpret_cast<const float4*>(&bias[gc]);
                    int ii = ih * 4 + i;
                    int jj = jh * 4;
                    float4 r = make_float4(acc[ii][jj + 0] + bz.x,
                                           acc[ii][jj + 1] + bz.y,
                                           acc[ii][jj + 2] + bz.z,
                                           acc[ii][jj + 3] + bz.w);
                    *reinterpret_cast<float4*>(&C[(size_t)gr * N + gc]) = r;
                }
            }
        }
    }
}

// ===========================================================================
// Fused flash attention, tf32 MMA.  One CTA = (b,h) head x 64-query tile.
// 128 threads = 4 warps, warp w owns queries [q0+16w, q0+16w+16).
//   pass 0: 16 local key tiles (online softmax)
//   pass 1: 64 projected-memory keys (separate softmax), results summed.
// Q fragments register-resident (pre-scaled by 1/8, tf32).
// Ksm [key][d] stride 76, Vsm [key][d] stride 72: conflict-free B-frag LDS.
// S->P fragment relayout done in-register via shfl (no smem round trip).
// ===========================================================================
#define KST 76
#define VST 72

__global__ __launch_bounds__(128) void attn_mma_kernel(
    const float* __restrict__ qkv, const float* __restrict__ memproj,
    float* __restrict__ attn)
{
    __shared__ __align__(16) float Ksm[64 * KST];   // 19456 B
    __shared__ __align__(16) float Vsm[64 * VST];   // 18432 B

    const int tid  = threadIdx.x;
    const int warp = tid >> 5;
    const int lane = tid & 31;
    const int gid  = lane >> 2;
    const int tg   = lane & 3;
    const int b    = blockIdx.y / HEADS;
    const int h    = blockIdx.y % HEADS;
    const int q0   = blockIdx.x * 64;
    const int qrow = q0 + warp * 16;

    // Q fragments (A operand, k over d=64 -> 8 chunks), scale folded in
    uint32_t aq[8][4];
    {
        const float* qb = &qkv[(size_t)(b * SEQ + qrow) * QKVW + h * HDIM];
#pragma unroll
        for (int kc = 0; kc < 8; kc++) {
            int k = kc * 8 + tg;
            aq[kc][0] = f2tf32(qb[(size_t)gid * QKVW + k] * 0.125f);
            aq[kc][1] = f2tf32(qb[(size_t)(gid + 8) * QKVW + k] * 0.125f);
            aq[kc][2] = f2tf32(qb[(size_t)gid * QKVW + k + 4] * 0.125f);
            aq[kc][3] = f2tf32(qb[(size_t)(gid + 8) * QKVW + k + 4] * 0.125f);
        }
    }

    float o[8][4], ofin[8][4], m_r[2], l_r[2];
#pragma unroll
    for (int nf = 0; nf < 8; nf++)
#pragma unroll
        for (int e = 0; e < 4; e++) { o[nf][e] = 0.f; ofin[nf][e] = 0.f; }
    m_r[0] = m_r[1] = -1e30f;
    l_r[0] = l_r[1] = 0.f;

    for (int pass = 0; pass < 2; pass++) {
        const int ntiles = (pass == 0) ? (SEQ / 64) : 1;
        for (int kt = 0; kt < ntiles; kt++) {
            __syncthreads();   // protect smem reuse across tiles

            // ---- stage K,V tile (tf32) ----
#pragma unroll
            for (int i = 0; i < 8; i++) {
                int idx = tid + i * 128;
                int r   = idx >> 4;
                int d4  = (idx & 15) << 2;
                float4 kv, vv;
                if (pass == 0) {
                    size_t base = (size_t)(b * SEQ + kt * 64 + r) * QKVW + h * HDIM + d4;
                    kv = *reinterpret_cast<const float4*>(&qkv[base + EMB]);
                    vv = *reinterpret_cast<const float4*>(&qkv[base + 2 * EMB]);
                } else {
                    size_t base = (size_t)r * EMB + h * HDIM + d4;
                    kv = *reinterpret_cast<const float4*>(&memproj[base]);
                    vv = kv;   // memory acts as both K and V
                }
                uint4 uk = make_uint4(f2tf32(kv.x), f2tf32(kv.y), f2tf32(kv.z), f2tf32(kv.w));
                uint4 uv = make_uint4(f2tf32(vv.x), f2tf32(vv.y), f2tf32(vv.z), f2tf32(vv.w));
                *reinterpret_cast<uint4*>(&Ksm[r * KST + d4]) = uk;
                *reinterpret_cast<uint4*>(&Vsm[r * VST + d4]) = uv;
            }
            __syncthreads();

            // ---- S = (Q/8) K^T : 8 n-frags (keys) x 8 k-chunks (d) ----
            float s[8][4];
#pragma unroll
            for (int nf = 0; nf < 8; nf++)
#pragma unroll
                for (int e = 0; e < 4; e++) s[nf][e] = 0.f;

#pragma unroll
            for (int nf = 0; nf < 8; nf++) {
                const int krow = nf * 8 + gid;
#pragma unroll
                for (int kc = 0; kc < 8; kc++) {
                    uint32_t bf[2];
                    bf[0] = __float_as_uint(Ksm[krow * KST + kc * 8 + tg]);
                    bf[1] = __float_as_uint(Ksm[krow * KST + kc * 8 + tg + 4]);
                    mma_tf32(s[nf], aq[kc], bf, s[nf]);
                }
            }

            // ---- online softmax (rows gid / gid+8; reduce over 4 tg lanes) ----
#pragma unroll
            for (int rh = 0; rh < 2; rh++) {
                float rm = -1e30f;
#pragma unroll
                for (int nf = 0; nf < 8; nf++)
                    rm = fmaxf(rm, fmaxf(s[nf][2 * rh], s[nf][2 * rh + 1]));
                rm = fmaxf(rm, __shfl_xor_sync(0xffffffffu, rm, 1));
                rm = fmaxf(rm, __shfl_xor_sync(0xffffffffu, rm, 2));
                float mnew = fmaxf(m_r[rh], rm);
                float fac  = __expf(m_r[rh] - mnew);
                float rs   = 0.f;
#pragma unroll
                for (int nf = 0; nf < 8; nf++) {
                    s[nf][2 * rh]     = __expf(s[nf][2 * rh] - mnew);
                    s[nf][2 * rh + 1] = __expf(s[nf][2 * rh + 1] - mnew);
                    rs += s[nf][2 * rh] + s[nf][2 * rh + 1];
                }
                rs += __shfl_xor_sync(0xffffffffu, rs, 1);
                rs += __shfl_xor_sync(0xffffffffu, rs, 2);
                l_r[rh] = l_r[rh] * fac + rs;
                m_r[rh] = mnew;
#pragma unroll
                for (int nf = 0; nf < 8; nf++) {
                    o[nf][2 * rh]     *= fac;
                    o[nf][2 * rh + 1] *= fac;
                }
            }

            // ---- O += P V : P A-frags built from S C-frags via shfl ----
#pragma unroll
            for (int kc = 0; kc < 8; kc++) {
                // A-frag kc needs P cols kc*8+tg (+4); owner lane has same gid,
                // tg_src = tg>>1 (or +2), element c0/c1 (rows gid) c2/c3 (gid+8).
                const int src  = (gid << 2) | (tg >> 1);
                const int src2 = src + 2;
                float v0 = __shfl_sync(0xffffffffu, s[kc][0], src);
                float v1 = __shfl_sync(0xffffffffu, s[kc][1], src);
                float v2 = __shfl_sync(0xffffffffu, s[kc][2], src);
                float v3 = __shfl_sync(0xffffffffu, s[kc][3], src);
                float w0 = __shfl_sync(0xffffffffu, s[kc][0], src2);
                float w1 = __shfl_sync(0xffffffffu, s[kc][1], src2);
                float w2 = __shfl_sync(0xffffffffu, s[kc][2], src2);
                float w3 = __shfl_sync(0xffffffffu, s[kc][3], src2);
                const bool odd = tg & 1;
                uint32_t ap[4];
                ap[0] = f2tf32(odd ? v1 : v0);
                ap[1] = f2tf32(odd ? v3 : v2);
                ap[2] = f2tf32(odd ? w1 : w0);
                ap[3] = f2tf32(odd ? w3 : w2);

                const int kr = kc * 8 + tg;
#pragma unroll
                for (int nf = 0; nf < 8; nf++) {
                    uint32_t bf[2];
                    bf[0] = __float_as_uint(Vsm[kr * VST + nf * 8 + gid]);
                    bf[1] = __float_as_uint(Vsm[(kr + 4) * VST + nf * 8 + gid]);
                    mma_tf32(o[nf], ap, bf, o[nf]);
                }
            }
        }

        // ---- finalize this softmax pass ----
#pragma unroll
        for (int rh = 0; rh < 2; rh++) {
            float inv = 1.0f / l_r[rh];
#pragma unroll
            for (int nf = 0; nf < 8; nf++) {
                ofin[nf][2 * rh]     += o[nf][2 * rh] * inv;
                ofin[nf][2 * rh + 1] += o[nf][2 * rh + 1] * inv;
                o[nf][2 * rh] = 0.f;
                o[nf][2 * rh + 1] = 0.f;
            }
            m_r[rh] = -1e30f;
            l_r[rh] = 0.f;
        }
    }

    // ---- write head-interleaved output ----
#pragma unroll
    for (int nf = 0; nf < 8; nf++) {
        int col = h * HDIM + nf * 8 + 2 * tg;
        size_t i0 = (size_t)(b * SEQ + qrow + gid) * EMB + col;
        size_t i1 = (size_t)(b * SEQ + qrow + gid + 8) * EMB + col;
        *reinterpret_cast<float2*>(&attn[i0]) = make_float2(ofin[nf][0], ofin[nf][1]);
        *reinterpret_cast<float2*>(&attn[i1]) = make_float2(ofin[nf][2], ofin[nf][3]);
    }
}

// ---------------------------------------------------------------------------
// Launch
// ---------------------------------------------------------------------------
extern "C" void kernel_launch(void* const* d_in, const int* in_sizes, int n_in,
                              void* d_out, int out_size)
{
    const float* x      = (const float*)d_in[0];
    const float* w_qkv  = (const float*)d_in[1];
    const float* b_qkv  = (const float*)d_in[2];
    const float* w_out  = (const float*)d_in[3];
    const float* b_out  = (const float*)d_in[4];
    const float* w_mem  = (const float*)d_in[5];
    const float* b_mem  = (const float*)d_in[6];
    const float* memory = (const float*)d_in[7];
    float* out = (float*)d_out;

    float *qkv, *attn, *memp, *wqkvT, *woutT;
    cudaGetSymbolAddress((void**)&qkv,   g_qkv);
    cudaGetSymbolAddress((void**)&attn,  g_attn);
    cudaGetSymbolAddress((void**)&memp,  g_memproj);
    cudaGetSymbolAddress((void**)&wqkvT, g_wqkvT);
    cudaGetSymbolAddress((void**)&woutT, g_woutT);

    // 0) weight transposes -> [N,K] for the MMA B operand
    {
        dim3 blk(32, 8);
        transpose_kernel<<<dim3(QKVW / 32, EMB / 32), blk>>>(w_qkv, wqkvT, EMB, QKVW);
        transpose_kernel<<<dim3(EMB / 32, EMB / 32), blk>>>(w_out, woutT, EMB, EMB);
    }
    // 1) QKV projection (tf32 mma): [8192,768] @ [768,2304] + b
    {
        dim3 grid(QKVW / 128, NTOK / 128);
        gemm_mma_kernel<<<grid, 256>>>(x, wqkvT, b_qkv, qkv, NTOK, QKVW, EMB);
    }
    // 2) Memory projection (SIMT, tiny): [64,768] @ [768,768] + b
    {
        dim3 grid(EMB / 128, 1);
        sgemm_bias_kernel<<<grid, 256>>>(memory, w_mem, b_mem, memp, MEMSZ, EMB, EMB);
    }
    // 3) Fused local + memory attention (tf32 mma)
    {
        dim3 grid(SEQ / 64, BATCH * HEADS);
        attn_mma_kernel<<<grid, 128>>>(qkv, memp, attn);
    }
    // 4) Output projection (tf32 mma): [8192,768] @ [768,768] + b
    {
        dim3 grid(EMB / 128, NTOK / 128);
        gemm_mma_kernel<<<grid, 256>>>(attn, woutT, b_out, out, NTOK, EMB, EMB);
    }
}

// round 9
// speedup vs baseline: 2.7334x; 1.0808x over previous
#include <cuda_runtime.h>
#include <cuda_bf16.h>
#include <cstdint>
#include <cstddef>

// ---------------------------------------------------------------------------
// InfiniAttention: B=8, T=1024, C=768, H=12, D=64, MEM=64
// tf32 mma.sync everywhere big; cp.async double-buffered pipelines.
// ---------------------------------------------------------------------------

#define BATCH 8
#define SEQ   1024
#define EMB   768
#define HEADS 12
#define HDIM  64
#define MEMSZ 64
#define NTOK  (BATCH * SEQ)       // 8192
#define QKVW  (3 * EMB)           // 2304
#define KSLICES 8                 // memproj split-K

// Scratch (device globals; no runtime allocation allowed)
__device__ float g_qkv[NTOK * QKVW];          // 75.5 MB
__device__ float g_attn[NTOK * EMB];          // 25.2 MB
__device__ float g_memproj[MEMSZ * EMB];      // 192 KB
__device__ float g_mempart[KSLICES * MEMSZ * EMB];  // 1.5 MB
__device__ float g_wqkvT[QKVW * EMB];         // 7.1 MB
__device__ float g_woutT[EMB * EMB];          // 2.25 MB

// ===========================================================================
// helpers
// ===========================================================================
__device__ __forceinline__ uint32_t smem_u32(const void* p) {
    uint32_t a;
    asm("{ .reg .u64 t; cvta.to.shared.u64 t, %1; cvt.u32.u64 %0, t; }"
        : "=r"(a) : "l"(p));
    return a;
}

__device__ __forceinline__ void mma_tf32(float d[4], const uint32_t a[4],
                                         const uint32_t b[2], const float c[4]) {
    asm volatile(
        "mma.sync.aligned.m16n8k8.row.col.f32.tf32.tf32.f32 "
        "{%0,%1,%2,%3}, {%4,%5,%6,%7}, {%8,%9}, {%10,%11,%12,%13};"
        : "=f"(d[0]), "=f"(d[1]), "=f"(d[2]), "=f"(d[3])
        : "r"(a[0]), "r"(a[1]), "r"(a[2]), "r"(a[3]),
          "r"(b[0]), "r"(b[1]),
          "f"(c[0]), "f"(c[1]), "f"(c[2]), "f"(c[3]));
}

__device__ __forceinline__ uint32_t f2tf32(float f) {
    uint32_t u;
    asm("cvt.rna.tf32.f32 %0, %1;" : "=r"(u) : "f"(f));
    return u;
}
__device__ __forceinline__ uint32_t ld2tf32(const float* p) { return f2tf32(*p); }

#define CP_ASYNC16(dst_u32, src_ptr) \
    asm volatile("cp.async.cg.shared.global [%0], [%1], 16;" \
                 :: "r"(dst_u32), "l"(src_ptr) : "memory")
#define CP_COMMIT() asm volatile("cp.async.commit_group;" ::: "memory")
#define CP_WAIT0()  asm volatile("cp.async.wait_group 0;" ::: "memory")

// ===========================================================================
// Transpose: out[c][r] = in[r][c].  R, C multiples of 32. block (32,8).
// ===========================================================================
__global__ void transpose_kernel(const float* __restrict__ in, float* __restrict__ out,
                                 int R, int C)
{
    __shared__ float t[32][33];
    int c0 = blockIdx.x * 32, r0 = blockIdx.y * 32;
    int x = threadIdx.x, y = threadIdx.y;
#pragma unroll
    for (int i = 0; i < 32; i += 8)
        t[y + i][x] = in[(size_t)(r0 + y + i) * C + c0 + x];
    __syncthreads();
#pragma unroll
    for (int i = 0; i < 32; i += 8)
        out[(size_t)(c0 + y + i) * R + r0 + x] = t[x][y + i];
}

// ===========================================================================
// tf32 MMA GEMM + bias, cp.async double-buffered.
// C[M,N] = A[M,K] @ BT[N,K]^T + bias[N]; 128x128x32 tile, 256 threads.
// Dynamic smem: 2 buffers x (A 128x36 + B 128x36) floats = 73728 B.
// ===========================================================================
#define GEMM_SMEM 73728

__global__ __launch_bounds__(256) void gemm_mma_kernel(
    const float* __restrict__ A, const float* __restrict__ BT,
    const float* __restrict__ bias, float* __restrict__ C,
    int M, int N, int K)
{
    extern __shared__ __align__(16) float sm[];
    const uint32_t sb = smem_u32(sm);

    const int tid  = threadIdx.x;
    const int lane = tid & 31;
    const int warp = tid >> 5;
    const int gid  = lane >> 2;
    const int tg   = lane & 3;
    const int m0   = (warp & 3) * 32;
    const int n0   = (warp >> 2) * 64;
    const int row0 = blockIdx.y * 128;
    const int col0 = blockIdx.x * 128;

    float acc[2][8][4];
#pragma unroll
    for (int i = 0; i < 2; i++)
#pragma unroll
        for (int j = 0; j < 8; j++)
#pragma unroll
            for (int e = 0; e < 4; e++) acc[i][j][e] = 0.f;

    const int nkt = K / 32;

    // stage tile kt into buffer s
    auto stage = [&](int kt, int s) {
        const int k0 = kt * 32;
        const uint32_t ab = sb + s * 36864u;
        const uint32_t bb = ab + 18432u;
#pragma unroll
        for (int i = 0; i < 4; i++) {
            int f = tid + i * 256;           // 0..1023
            int m = f >> 3;
            int k4 = (f & 7) * 4;
            CP_ASYNC16(ab + (m * 36 + k4) * 4, &A [(size_t)(row0 + m) * K + k0 + k4]);
            CP_ASYNC16(bb + (m * 36 + k4) * 4, &BT[(size_t)(col0 + m) * K + k0 + k4]);
        }
        CP_COMMIT();
    };

    stage(0, 0);

    for (int kt = 0; kt < nkt; kt++) {
        CP_WAIT0();
        __syncthreads();
        if (kt + 1 < nkt) stage(kt + 1, (kt + 1) & 1);

        const float* As = sm + (kt & 1) * 9216;
        const float* Bs = As + 4608;

#pragma unroll
        for (int kc = 0; kc < 4; kc++) {
            const int kb = kc * 8;
            uint32_t af[2][4];
#pragma unroll
            for (int mf = 0; mf < 2; mf++) {
                int mr = m0 + mf * 16 + gid;
                af[mf][0] = ld2tf32(&As[mr * 36 + kb + tg]);
                af[mf][1] = ld2tf32(&As[(mr + 8) * 36 + kb + tg]);
                af[mf][2] = ld2tf32(&As[mr * 36 + kb + tg + 4]);
                af[mf][3] = ld2tf32(&As[(mr + 8) * 36 + kb + tg + 4]);
            }
#pragma unroll
            for (int nf = 0; nf < 8; nf++) {
                int nr = n0 + nf * 8 + gid;
                uint32_t bf[2];
                bf[0] = ld2tf32(&Bs[nr * 36 + kb + tg]);
                bf[1] = ld2tf32(&Bs[nr * 36 + kb + tg + 4]);
                mma_tf32(acc[0][nf], af[0], bf, acc[0][nf]);
                mma_tf32(acc[1][nf], af[1], bf, acc[1][nf]);
            }
        }
        __syncthreads();
    }

#pragma unroll
    for (int mf = 0; mf < 2; mf++) {
#pragma unroll
        for (int nf = 0; nf < 8; nf++) {
            int row = row0 + m0 + mf * 16 + gid;
            int col = col0 + n0 + nf * 8 + 2 * tg;
            float2 bz = *reinterpret_cast<const float2*>(&bias[col]);
            *reinterpret_cast<float2*>(&C[(size_t)row * N + col]) =
                make_float2(acc[mf][nf][0] + bz.x, acc[mf][nf][1] + bz.y);
            *reinterpret_cast<float2*>(&C[(size_t)(row + 8) * N + col]) =
                make_float2(acc[mf][nf][2] + bz.x, acc[mf][nf][3] + bz.y);
        }
    }
}

// ===========================================================================
// Memory projection, split-K SIMT: grid (12 n-tiles, 8 k-slices), 256 thr.
// part[s][64][768] tile = memory[64, 96s:96s+96] @ w_mem[96 slice, 64 cols]
// ===========================================================================
__global__ __launch_bounds__(256) void memproj_splitk_kernel(
    const float* __restrict__ mem, const float* __restrict__ w,
    float* __restrict__ part)
{
    __shared__ float As[16][64];   // [k][row]
    __shared__ float Bs[16][68];   // [k][col] (pad 4)

    const int tid = threadIdx.x;
    const int tx  = tid & 15;
    const int ty  = tid >> 4;
    const int nt  = blockIdx.x;        // column tile (64 cols)
    const int s   = blockIdx.y;        // k-slice
    const int kbase = s * 96;
    const int col0  = nt * 64;

    float acc[4][4];
#pragma unroll
    for (int i = 0; i < 4; i++)
#pragma unroll
        for (int j = 0; j < 4; j++) acc[i][j] = 0.f;

    for (int k0 = 0; k0 < 96; k0 += 16) {
        {   // A: 64 rows x 16 k -> transposed
            int f  = tid * 4;
            int r  = f >> 4;          // 0..63
            int c4 = f & 15;          // 0,4,8,12
            float4 v = *reinterpret_cast<const float4*>(
                &mem[(size_t)r * EMB + kbase + k0 + c4]);
            As[c4 + 0][r] = v.x; As[c4 + 1][r] = v.y;
            As[c4 + 2][r] = v.z; As[c4 + 3][r] = v.w;
        }
        {   // B: 16 k x 64 cols
            int f  = tid * 4;
            int r  = f >> 6;          // 0..15
            int c4 = f & 63;
            float4 v = *reinterpret_cast<const float4*>(
                &w[(size_t)(kbase + k0 + r) * EMB + col0 + c4]);
            *reinterpret_cast<float4*>(&Bs[r][c4]) = v;
        }
        __syncthreads();
#pragma unroll
        for (int kk = 0; kk < 16; kk++) {
            float a[4], b[4];
#pragma unroll
            for (int i = 0; i < 4; i++) a[i] = As[kk][ty * 4 + i];
#pragma unroll
            for (int j = 0; j < 4; j++) b[j] = Bs[kk][tx * 4 + j];
#pragma unroll
            for (int i = 0; i < 4; i++)
#pragma unroll
                for (int j = 0; j < 4; j++)
                    acc[i][j] = fmaf(a[i], b[j], acc[i][j]);
        }
        __syncthreads();
    }

#pragma unroll
    for (int i = 0; i < 4; i++) {
        int row = ty * 4 + i;
        *reinterpret_cast<float4*>(
            &part[(size_t)(s * MEMSZ + row) * EMB + col0 + tx * 4]) =
            make_float4(acc[i][0], acc[i][1], acc[i][2], acc[i][3]);
    }
}

// reduce 8 partials + bias -> memproj ; grid 48 x 256 threads, float4 each
__global__ __launch_bounds__(256) void memproj_reduce_kernel(
    const float* __restrict__ part, const float* __restrict__ bias,
    float* __restrict__ outp)
{
    int i4 = (blockIdx.x * 256 + threadIdx.x) * 4;   // 0..49148
    int col = i4 % EMB;
    float4 s = *reinterpret_cast<const float4*>(&bias[col]);
#pragma unroll
    for (int sl = 0; sl < KSLICES; sl++) {
        float4 p = *reinterpret_cast<const float4*>(&part[(size_t)sl * MEMSZ * EMB + i4]);
        s.x += p.x; s.y += p.y; s.z += p.z; s.w += p.w;
    }
    *reinterpret_cast<float4*>(&outp[i4]) = s;
}

// ===========================================================================
// Fused flash attention, tf32 MMA, cp.async double-buffered.
// CTA = (b,h) x 128 queries; 256 threads (8 warps x 16 q).
// 17 key tiles: 16 local + 1 memory (K=V=memproj); softmax split at tile 16.
// Smem: 2 x (K 64x76 + V 64x72) floats = 75776 B dynamic.
// ===========================================================================
#define KST 76
#define VST 72
#define ATTN_SMEM 75776

__global__ __launch_bounds__(256) void attn_mma_kernel(
    const float* __restrict__ qkv, const float* __restrict__ memproj,
    float* __restrict__ attn)
{
    extern __shared__ __align__(16) float sm[];
    const uint32_t sb = smem_u32(sm);

    const int tid  = threadIdx.x;
    const int warp = tid >> 5;
    const int lane = tid & 31;
    const int gid  = lane >> 2;
    const int tg   = lane & 3;
    const int b    = blockIdx.y / HEADS;
    const int h    = blockIdx.y % HEADS;
    const int qrow = blockIdx.x * 128 + warp * 16;

    // Q fragments (A operand over d=64 -> 8 k-chunks), 1/8 scale folded in
    uint32_t aq[8][4];
    {
        const float* qb = &qkv[(size_t)(b * SEQ + qrow) * QKVW + h * HDIM];
#pragma unroll
        for (int kc = 0; kc < 8; kc++) {
            int k = kc * 8 + tg;
            aq[kc][0] = f2tf32(qb[(size_t)gid * QKVW + k] * 0.125f);
            aq[kc][1] = f2tf32(qb[(size_t)(gid + 8) * QKVW + k] * 0.125f);
            aq[kc][2] = f2tf32(qb[(size_t)gid * QKVW + k + 4] * 0.125f);
            aq[kc][3] = f2tf32(qb[(size_t)(gid + 8) * QKVW + k + 4] * 0.125f);
        }
    }

    float o[8][4], ofin[8][4], m_r[2], l_r[2];
#pragma unroll
    for (int nf = 0; nf < 8; nf++)
#pragma unroll
        for (int e = 0; e < 4; e++) { o[nf][e] = 0.f; ofin[nf][e] = 0.f; }
    m_r[0] = m_r[1] = -1e30f;
    l_r[0] = l_r[1] = 0.f;

    // stage tile t into buffer s (K+V; tile 16 = memory tile)
    auto stage = [&](int t, int s) {
        const uint32_t kb = sb + s * 37888u;
        const uint32_t vb = kb + 19456u;
#pragma unroll
        for (int i = 0; i < 4; i++) {
            int idx = tid + i * 256;          // 0..1023
            int r   = idx >> 4;
            int c4  = (idx & 15) * 4;
            const float *srcK, *srcV;
            if (t < 16) {
                size_t base = (size_t)(b * SEQ + t * 64 + r) * QKVW + h * HDIM + c4;
                srcK = &qkv[base + EMB];
                srcV = &qkv[base + 2 * EMB];
            } else {
                srcK = &memproj[(size_t)r * EMB + h * HDIM + c4];
                srcV = srcK;
            }
            CP_ASYNC16(kb + (r * KST + c4) * 4, srcK);
            CP_ASYNC16(vb + (r * VST + c4) * 4, srcV);
        }
        CP_COMMIT();
    };

    stage(0, 0);

    for (int t = 0; t < 17; t++) {
        CP_WAIT0();
        __syncthreads();
        if (t + 1 < 17) stage(t + 1, (t + 1) & 1);

        const float* Ksm = sm + (t & 1) * 9472;
        const float* Vsm = Ksm + 4864;

        // ---- S = (Q/8) K^T ----
        float s[8][4];
#pragma unroll
        for (int nf = 0; nf < 8; nf++)
#pragma unroll
            for (int e = 0; e < 4; e++) s[nf][e] = 0.f;

#pragma unroll
        for (int nf = 0; nf < 8; nf++) {
            const int krow = nf * 8 + gid;
#pragma unroll
            for (int kc = 0; kc < 8; kc++) {
                uint32_t bf[2];
                bf[0] = ld2tf32(&Ksm[krow * KST + kc * 8 + tg]);
                bf[1] = ld2tf32(&Ksm[krow * KST + kc * 8 + tg + 4]);
                mma_tf32(s[nf], aq[kc], bf, s[nf]);
            }
        }

        // ---- online softmax ----
#pragma unroll
        for (int rh = 0; rh < 2; rh++) {
            float rm = -1e30f;
#pragma unroll
            for (int nf = 0; nf < 8; nf++)
                rm = fmaxf(rm, fmaxf(s[nf][2 * rh], s[nf][2 * rh + 1]));
            rm = fmaxf(rm, __shfl_xor_sync(0xffffffffu, rm, 1));
            rm = fmaxf(rm, __shfl_xor_sync(0xffffffffu, rm, 2));
            float mnew = fmaxf(m_r[rh], rm);
            float fac  = __expf(m_r[rh] - mnew);
            float rs   = 0.f;
#pragma unroll
            for (int nf = 0; nf < 8; nf++) {
                s[nf][2 * rh]     = __expf(s[nf][2 * rh] - mnew);
                s[nf][2 * rh + 1] = __expf(s[nf][2 * rh + 1] - mnew);
                rs += s[nf][2 * rh] + s[nf][2 * rh + 1];
            }
            rs += __shfl_xor_sync(0xffffffffu, rs, 1);
            rs += __shfl_xor_sync(0xffffffffu, rs, 2);
            l_r[rh] = l_r[rh] * fac + rs;
            m_r[rh] = mnew;
#pragma unroll
            for (int nf = 0; nf < 8; nf++) {
                o[nf][2 * rh]     *= fac;
                o[nf][2 * rh + 1] *= fac;
            }
        }

        // ---- O += P V (P A-frags via in-register shfl relayout) ----
#pragma unroll
        for (int kc = 0; kc < 8; kc++) {
            const int src  = (gid << 2) | (tg >> 1);
            const int src2 = src + 2;
            float v0 = __shfl_sync(0xffffffffu, s[kc][0], src);
            float v1 = __shfl_sync(0xffffffffu, s[kc][1], src);
            float v2 = __shfl_sync(0xffffffffu, s[kc][2], src);
            float v3 = __shfl_sync(0xffffffffu, s[kc][3], src);
            float w0 = __shfl_sync(0xffffffffu, s[kc][0], src2);
            float w1 = __shfl_sync(0xffffffffu, s[kc][1], src2);
            float w2 = __shfl_sync(0xffffffffu, s[kc][2], src2);
            float w3 = __shfl_sync(0xffffffffu, s[kc][3], src2);
            const bool odd = tg & 1;
            uint32_t ap[4];
            ap[0] = f2tf32(odd ? v1 : v0);
            ap[1] = f2tf32(odd ? v3 : v2);
            ap[2] = f2tf32(odd ? w1 : w0);
            ap[3] = f2tf32(odd ? w3 : w2);

            const int kr = kc * 8 + tg;
#pragma unroll
            for (int nf = 0; nf < 8; nf++) {
                uint32_t bf[2];
                bf[0] = ld2tf32(&Vsm[kr * VST + nf * 8 + gid]);
                bf[1] = ld2tf32(&Vsm[(kr + 4) * VST + nf * 8 + gid]);
                mma_tf32(o[nf], ap, bf, o[nf]);
            }
        }

        // ---- finalize softmax pass at local/memory boundary and at end ----
        if (t == 15 || t == 16) {
#pragma unroll
            for (int rh = 0; rh < 2; rh++) {
                float inv = 1.0f / l_r[rh];
#pragma unroll
                for (int nf = 0; nf < 8; nf++) {
                    ofin[nf][2 * rh]     += o[nf][2 * rh] * inv;
                    ofin[nf][2 * rh + 1] += o[nf][2 * rh + 1] * inv;
                    o[nf][2 * rh] = 0.f;
                    o[nf][2 * rh + 1] = 0.f;
                }
                m_r[rh] = -1e30f;
                l_r[rh] = 0.f;
            }
        }
        __syncthreads();
    }

    // ---- write head-interleaved output ----
#pragma unroll
    for (int nf = 0; nf < 8; nf++) {
        int col = h * HDIM + nf * 8 + 2 * tg;
        size_t i0 = (size_t)(b * SEQ + qrow + gid) * EMB + col;
        size_t i1 = (size_t)(b * SEQ + qrow + gid + 8) * EMB + col;
        *reinterpret_cast<float2*>(&attn[i0]) = make_float2(ofin[nf][0], ofin[nf][1]);
        *reinterpret_cast<float2*>(&attn[i1]) = make_float2(ofin[nf][2], ofin[nf][3]);
    }
}

// ---------------------------------------------------------------------------
// Launch
// ---------------------------------------------------------------------------
extern "C" void kernel_launch(void* const* d_in, const int* in_sizes, int n_in,
                              void* d_out, int out_size)
{
    const float* x      = (const float*)d_in[0];
    const float* w_qkv  = (const float*)d_in[1];
    const float* b_qkv  = (const float*)d_in[2];
    const float* w_out  = (const float*)d_in[3];
    const float* b_out  = (const float*)d_in[4];
    const float* w_mem  = (const float*)d_in[5];
    const float* b_mem  = (const float*)d_in[6];
    const float* memory = (const float*)d_in[7];
    float* out = (float*)d_out;

    float *qkv, *attn, *memp, *mpart, *wqkvT, *woutT;
    cudaGetSymbolAddress((void**)&qkv,   g_qkv);
    cudaGetSymbolAddress((void**)&attn,  g_attn);
    cudaGetSymbolAddress((void**)&memp,  g_memproj);
    cudaGetSymbolAddress((void**)&mpart, g_mempart);
    cudaGetSymbolAddress((void**)&wqkvT, g_wqkvT);
    cudaGetSymbolAddress((void**)&woutT, g_woutT);

    cudaFuncSetAttribute(gemm_mma_kernel,
                         cudaFuncAttributeMaxDynamicSharedMemorySize, GEMM_SMEM);
    cudaFuncSetAttribute(attn_mma_kernel,
                         cudaFuncAttributeMaxDynamicSharedMemorySize, ATTN_SMEM);

    // 0) weight transposes -> [N,K] for MMA B operand
    {
        dim3 blk(32, 8);
        transpose_kernel<<<dim3(QKVW / 32, EMB / 32), blk>>>(w_qkv, wqkvT, EMB, QKVW);
        transpose_kernel<<<dim3(EMB / 32, EMB / 32), blk>>>(w_out, woutT, EMB, EMB);
    }
    // 1) memory projection split-K (96 CTAs) + reduce
    {
        memproj_splitk_kernel<<<dim3(EMB / 64, KSLICES), 256>>>(memory, w_mem, mpart);
        memproj_reduce_kernel<<<MEMSZ * EMB / (256 * 4), 256>>>(mpart, b_mem, memp);
    }
    // 2) QKV projection (tf32 mma): [8192,768] @ [768,2304] + b
    {
        dim3 grid(QKVW / 128, NTOK / 128);
        gemm_mma_kernel<<<grid, 256, GEMM_SMEM>>>(x, wqkvT, b_qkv, qkv, NTOK, QKVW, EMB);
    }
    // 3) fused local + memory attention (tf32 mma)
    {
        dim3 grid(SEQ / 128, BATCH * HEADS);
        attn_mma_kernel<<<grid, 256, ATTN_SMEM>>>(qkv, memp, attn);
    }
    // 4) output projection (tf32 mma): [8192,768] @ [768,768] + b
    {
        dim3 grid(EMB / 128, NTOK / 128);
        gemm_mma_kernel<<<grid, 256, GEMM_SMEM>>>(attn, woutT, b_out, out, NTOK, EMB, EMB);
    }
}

// round 10
// speedup vs baseline: 3.2622x; 1.1934x over previous
#include <cuda_runtime.h>
#include <cuda_bf16.h>
#include <cstdint>
#include <cstddef>

// ---------------------------------------------------------------------------
// InfiniAttention: B=8, T=1024, C=768, H=12, D=64, MEM=64
// tf32 mma.sync; producer-side tf32 rounding (consumers do pure LDS);
// 3-stage cp.async GEMM pipeline, double-buffered flash attention.
// ---------------------------------------------------------------------------

#define BATCH 8
#define SEQ   1024
#define EMB   768
#define HEADS 12
#define HDIM  64
#define MEMSZ 64
#define NTOK  (BATCH * SEQ)       // 8192
#define QKVW  (3 * EMB)           // 2304
#define KSLICES 8                 // memproj split-K

// Scratch (device globals; no runtime allocation allowed)
__device__ float g_qkv[NTOK * QKVW];                // 75.5 MB (tf32-rounded)
__device__ float g_attn[NTOK * EMB];                // 25.2 MB (tf32-rounded)
__device__ float g_xr[NTOK * EMB];                  // 25.2 MB (x, tf32-rounded)
__device__ float g_memproj[MEMSZ * EMB];            // 192 KB  (tf32-rounded)
__device__ float g_mempart[KSLICES * MEMSZ * EMB];  // 1.5 MB
__device__ float g_wqkvT[QKVW * EMB];               // 7.1 MB  (tf32-rounded)
__device__ float g_woutT[EMB * EMB];                // 2.25 MB (tf32-rounded)

// ===========================================================================
// helpers
// ===========================================================================
__device__ __forceinline__ uint32_t smem_u32(const void* p) {
    uint32_t a;
    asm("{ .reg .u64 t; cvta.to.shared.u64 t, %1; cvt.u32.u64 %0, t; }"
        : "=r"(a) : "l"(p));
    return a;
}

__device__ __forceinline__ void mma_tf32(float d[4], const uint32_t a[4],
                                         const uint32_t b[2], const float c[4]) {
    asm volatile(
        "mma.sync.aligned.m16n8k8.row.col.f32.tf32.tf32.f32 "
        "{%0,%1,%2,%3}, {%4,%5,%6,%7}, {%8,%9}, {%10,%11,%12,%13};"
        : "=f"(d[0]), "=f"(d[1]), "=f"(d[2]), "=f"(d[3])
        : "r"(a[0]), "r"(a[1]), "r"(a[2]), "r"(a[3]),
          "r"(b[0]), "r"(b[1]),
          "f"(c[0]), "f"(c[1]), "f"(c[2]), "f"(c[3]));
}

__device__ __forceinline__ uint32_t f2tf32(float f) {
    uint32_t u;
    asm("cvt.rna.tf32.f32 %0, %1;" : "=r"(u) : "f"(f));
    return u;
}
// producer-side rounding: tf32 bit pattern stored as float
__device__ __forceinline__ float rnd(float f) { return __uint_as_float(f2tf32(f)); }
__device__ __forceinline__ float4 rnd4(float4 v) {
    return make_float4(rnd(v.x), rnd(v.y), rnd(v.z), rnd(v.w));
}

#define CP_ASYNC16(dst_u32, src_ptr) \
    asm volatile("cp.async.cg.shared.global [%0], [%1], 16;" \
                 :: "r"(dst_u32), "l"(src_ptr) : "memory")
#define CP_COMMIT() asm volatile("cp.async.commit_group;" ::: "memory")
#define CP_WAIT0()  asm volatile("cp.async.wait_group 0;" ::: "memory")
#define CP_WAIT1()  asm volatile("cp.async.wait_group 1;" ::: "memory")

// ===========================================================================
// x pre-round: tf32-round 8192x768 floats (float4 grid-stride)
// ===========================================================================
__global__ __launch_bounds__(256) void round_kernel(const float* __restrict__ in,
                                                    float* __restrict__ out, int n4)
{
    int i = blockIdx.x * 256 + threadIdx.x;
    if (i < n4) {
        float4 v = *reinterpret_cast<const float4*>(&in[i * 4]);
        *reinterpret_cast<float4*>(&out[i * 4]) = rnd4(v);
    }
}

// ===========================================================================
// Transpose + tf32 round: out[c][r] = rnd(in[r][c]).
// ===========================================================================
__global__ void transpose_kernel(const float* __restrict__ in, float* __restrict__ out,
                                 int R, int C)
{
    __shared__ float t[32][33];
    int c0 = blockIdx.x * 32, r0 = blockIdx.y * 32;
    int x = threadIdx.x, y = threadIdx.y;
#pragma unroll
    for (int i = 0; i < 32; i += 8)
        t[y + i][x] = rnd(in[(size_t)(r0 + y + i) * C + c0 + x]);
    __syncthreads();
#pragma unroll
    for (int i = 0; i < 32; i += 8)
        out[(size_t)(c0 + y + i) * R + r0 + x] = t[x][y + i];
}

// ===========================================================================
// tf32 MMA GEMM + bias, 3-stage cp.async, one sync per k-tile.
// C[M,N] = A[M,K] @ BT[N,K]^T + bias[N]; A/BT pre-rounded to tf32.
// 128x128x32 tile, 256 threads. Smem: 3 x (128x36 + 128x36) = 110592 B.
// RND_OUT: round C to tf32 (for intermediates feeding further MMAs).
// ===========================================================================
#define GEMM_SMEM 110592

template<bool RND_OUT>
__global__ __launch_bounds__(256) void gemm_mma_kernel(
    const float* __restrict__ A, const float* __restrict__ BT,
    const float* __restrict__ bias, float* __restrict__ C,
    int M, int N, int K)
{
    extern __shared__ __align__(16) float sm[];
    const uint32_t sb = smem_u32(sm);

    const int tid  = threadIdx.x;
    const int lane = tid & 31;
    const int warp = tid >> 5;
    const int gid  = lane >> 2;
    const int tg   = lane & 3;
    const int m0   = (warp & 3) * 32;
    const int n0   = (warp >> 2) * 64;
    const int row0 = blockIdx.y * 128;
    const int col0 = blockIdx.x * 128;

    float acc[2][8][4];
#pragma unroll
    for (int i = 0; i < 2; i++)
#pragma unroll
        for (int j = 0; j < 8; j++)
#pragma unroll
            for (int e = 0; e < 4; e++) acc[i][j][e] = 0.f;

    const int nkt = K / 32;

    auto stage = [&](int kt) {
        const int s  = kt % 3;
        const int k0 = kt * 32;
        const uint32_t ab = sb + s * 36864u;
        const uint32_t bb = ab + 18432u;
#pragma unroll
        for (int i = 0; i < 4; i++) {
            int f = tid + i * 256;
            int m = f >> 3;
            int k4 = (f & 7) * 4;
            CP_ASYNC16(ab + (m * 36 + k4) * 4, &A [(size_t)(row0 + m) * K + k0 + k4]);
            CP_ASYNC16(bb + (m * 36 + k4) * 4, &BT[(size_t)(col0 + m) * K + k0 + k4]);
        }
        CP_COMMIT();
    };

    stage(0);
    stage(1);

    for (int kt = 0; kt < nkt; kt++) {
        if (kt == nkt - 1) { CP_WAIT0(); } else { CP_WAIT1(); }
        __syncthreads();

        const float* As = sm + (kt % 3) * 9216;
        const float* Bs = As + 4608;

#pragma unroll
        for (int kc = 0; kc < 4; kc++) {
            const int kb = kc * 8;
            uint32_t af[2][4];
#pragma unroll
            for (int mf = 0; mf < 2; mf++) {
                int mr = m0 + mf * 16 + gid;
                af[mf][0] = __float_as_uint(As[mr * 36 + kb + tg]);
                af[mf][1] = __float_as_uint(As[(mr + 8) * 36 + kb + tg]);
                af[mf][2] = __float_as_uint(As[mr * 36 + kb + tg + 4]);
                af[mf][3] = __float_as_uint(As[(mr + 8) * 36 + kb + tg + 4]);
            }
#pragma unroll
            for (int nf = 0; nf < 8; nf++) {
                int nr = n0 + nf * 8 + gid;
                uint32_t bf[2];
                bf[0] = __float_as_uint(Bs[nr * 36 + kb + tg]);
                bf[1] = __float_as_uint(Bs[nr * 36 + kb + tg + 4]);
                mma_tf32(acc[0][nf], af[0], bf, acc[0][nf]);
                mma_tf32(acc[1][nf], af[1], bf, acc[1][nf]);
            }
        }

        if (kt + 2 < nkt) stage(kt + 2);
    }

#pragma unroll
    for (int mf = 0; mf < 2; mf++) {
#pragma unroll
        for (int nf = 0; nf < 8; nf++) {
            int row = row0 + m0 + mf * 16 + gid;
            int col = col0 + n0 + nf * 8 + 2 * tg;
            float2 bz = *reinterpret_cast<const float2*>(&bias[col]);
            float2 r0v = make_float2(acc[mf][nf][0] + bz.x, acc[mf][nf][1] + bz.y);
            float2 r1v = make_float2(acc[mf][nf][2] + bz.x, acc[mf][nf][3] + bz.y);
            if (RND_OUT) {
                r0v.x = rnd(r0v.x); r0v.y = rnd(r0v.y);
                r1v.x = rnd(r1v.x); r1v.y = rnd(r1v.y);
            }
            *reinterpret_cast<float2*>(&C[(size_t)row * N + col]) = r0v;
            *reinterpret_cast<float2*>(&C[(size_t)(row + 8) * N + col]) = r1v;
        }
    }
}

// ===========================================================================
// Memory projection, split-K SIMT + reduce (output tf32-rounded).
// ===========================================================================
__global__ __launch_bounds__(256) void memproj_splitk_kernel(
    const float* __restrict__ mem, const float* __restrict__ w,
    float* __restrict__ part)
{
    __shared__ float As[16][64];
    __shared__ float Bs[16][68];

    const int tid = threadIdx.x;
    const int tx  = tid & 15;
    const int ty  = tid >> 4;
    const int kbase = blockIdx.y * 96;
    const int col0  = blockIdx.x * 64;

    float acc[4][4];
#pragma unroll
    for (int i = 0; i < 4; i++)
#pragma unroll
        for (int j = 0; j < 4; j++) acc[i][j] = 0.f;

    for (int k0 = 0; k0 < 96; k0 += 16) {
        {
            int f  = tid * 4;
            int r  = f >> 4;
            int c4 = f & 15;
            float4 v = *reinterpret_cast<const float4*>(
                &mem[(size_t)r * EMB + kbase + k0 + c4]);
            As[c4 + 0][r] = v.x; As[c4 + 1][r] = v.y;
            As[c4 + 2][r] = v.z; As[c4 + 3][r] = v.w;
        }
        {
            int f  = tid * 4;
            int r  = f >> 6;
            int c4 = f & 63;
            *reinterpret_cast<float4*>(&Bs[r][c4]) =
                *reinterpret_cast<const float4*>(
                    &w[(size_t)(kbase + k0 + r) * EMB + col0 + c4]);
        }
        __syncthreads();
#pragma unroll
        for (int kk = 0; kk < 16; kk++) {
            float a[4], b[4];
#pragma unroll
            for (int i = 0; i < 4; i++) a[i] = As[kk][ty * 4 + i];
#pragma unroll
            for (int j = 0; j < 4; j++) b[j] = Bs[kk][tx * 4 + j];
#pragma unroll
            for (int i = 0; i < 4; i++)
#pragma unroll
                for (int j = 0; j < 4; j++)
                    acc[i][j] = fmaf(a[i], b[j], acc[i][j]);
        }
        __syncthreads();
    }

#pragma unroll
    for (int i = 0; i < 4; i++) {
        int row = ty * 4 + i;
        *reinterpret_cast<float4*>(
            &part[(size_t)(blockIdx.y * MEMSZ + row) * EMB + col0 + tx * 4]) =
            make_float4(acc[i][0], acc[i][1], acc[i][2], acc[i][3]);
    }
}

__global__ __launch_bounds__(256) void memproj_reduce_kernel(
    const float* __restrict__ part, const float* __restrict__ bias,
    float* __restrict__ outp)
{
    int i4 = (blockIdx.x * 256 + threadIdx.x) * 4;
    int col = i4 % EMB;
    float4 s = *reinterpret_cast<const float4*>(&bias[col]);
#pragma unroll
    for (int sl = 0; sl < KSLICES; sl++) {
        float4 p = *reinterpret_cast<const float4*>(&part[(size_t)sl * MEMSZ * EMB + i4]);
        s.x += p.x; s.y += p.y; s.z += p.z; s.w += p.w;
    }
    *reinterpret_cast<float4*>(&outp[i4]) = rnd4(s);
}

// ===========================================================================
// Fused flash attention, tf32 MMA, cp.async double-buffered.
// qkv/memproj pre-rounded -> fragment loads are pure LDS.
// CTA = (b,h) x 128 queries; 256 threads.
// ===========================================================================
#define KST 76
#define VST 72
#define ATTN_SMEM 75776

__global__ __launch_bounds__(256) void attn_mma_kernel(
    const float* __restrict__ qkv, const float* __restrict__ memproj,
    float* __restrict__ attn)
{
    extern __shared__ __align__(16) float sm[];
    const uint32_t sb = smem_u32(sm);

    const int tid  = threadIdx.x;
    const int warp = tid >> 5;
    const int lane = tid & 31;
    const int gid  = lane >> 2;
    const int tg   = lane & 3;
    const int b    = blockIdx.y / HEADS;
    const int h    = blockIdx.y % HEADS;
    const int qrow = blockIdx.x * 128 + warp * 16;

    // Q fragments, 1/8 scale folded (exact exponent shift on tf32 values)
    uint32_t aq[8][4];
    {
        const float* qb = &qkv[(size_t)(b * SEQ + qrow) * QKVW + h * HDIM];
#pragma unroll
        for (int kc = 0; kc < 8; kc++) {
            int k = kc * 8 + tg;
            aq[kc][0] = __float_as_uint(qb[(size_t)gid * QKVW + k] * 0.125f);
            aq[kc][1] = __float_as_uint(qb[(size_t)(gid + 8) * QKVW + k] * 0.125f);
            aq[kc][2] = __float_as_uint(qb[(size_t)gid * QKVW + k + 4] * 0.125f);
            aq[kc][3] = __float_as_uint(qb[(size_t)(gid + 8) * QKVW + k + 4] * 0.125f);
        }
    }

    float o[8][4], ofin[8][4], m_r[2], l_r[2];
#pragma unroll
    for (int nf = 0; nf < 8; nf++)
#pragma unroll
        for (int e = 0; e < 4; e++) { o[nf][e] = 0.f; ofin[nf][e] = 0.f; }
    m_r[0] = m_r[1] = -1e30f;
    l_r[0] = l_r[1] = 0.f;

    auto stage = [&](int t, int s) {
        const uint32_t kb = sb + s * 37888u;
        const uint32_t vb = kb + 19456u;
#pragma unroll
        for (int i = 0; i < 4; i++) {
            int idx = tid + i * 256;
            int r   = idx >> 4;
            int c4  = (idx & 15) * 4;
            const float *srcK, *srcV;
            if (t < 16) {
                size_t base = (size_t)(b * SEQ + t * 64 + r) * QKVW + h * HDIM + c4;
                srcK = &qkv[base + EMB];
                srcV = &qkv[base + 2 * EMB];
            } else {
                srcK = &memproj[(size_t)r * EMB + h * HDIM + c4];
                srcV = srcK;
            }
            CP_ASYNC16(kb + (r * KST + c4) * 4, srcK);
            CP_ASYNC16(vb + (r * VST + c4) * 4, srcV);
        }
        CP_COMMIT();
    };

    stage(0, 0);

    for (int t = 0; t < 17; t++) {
        CP_WAIT0();
        __syncthreads();
        if (t + 1 < 17) stage(t + 1, (t + 1) & 1);

        const float* Ksm = sm + (t & 1) * 9472;
        const float* Vsm = Ksm + 4864;

        // ---- S = (Q/8) K^T ----
        float s[8][4];
#pragma unroll
        for (int nf = 0; nf < 8; nf++)
#pragma unroll
            for (int e = 0; e < 4; e++) s[nf][e] = 0.f;

#pragma unroll
        for (int nf = 0; nf < 8; nf++) {
            const int krow = nf * 8 + gid;
#pragma unroll
            for (int kc = 0; kc < 8; kc++) {
                uint32_t bf[2];
                bf[0] = __float_as_uint(Ksm[krow * KST + kc * 8 + tg]);
                bf[1] = __float_as_uint(Ksm[krow * KST + kc * 8 + tg + 4]);
                mma_tf32(s[nf], aq[kc], bf, s[nf]);
            }
        }

        // ---- online softmax ----
#pragma unroll
        for (int rh = 0; rh < 2; rh++) {
            float rm = -1e30f;
#pragma unroll
            for (int nf = 0; nf < 8; nf++)
                rm = fmaxf(rm, fmaxf(s[nf][2 * rh], s[nf][2 * rh + 1]));
            rm = fmaxf(rm, __shfl_xor_sync(0xffffffffu, rm, 1));
            rm = fmaxf(rm, __shfl_xor_sync(0xffffffffu, rm, 2));
            float mnew = fmaxf(m_r[rh], rm);
            float fac  = __expf(m_r[rh] - mnew);
            float rs   = 0.f;
#pragma unroll
            for (int nf = 0; nf < 8; nf++) {
                s[nf][2 * rh]     = __expf(s[nf][2 * rh] - mnew);
                s[nf][2 * rh + 1] = __expf(s[nf][2 * rh + 1] - mnew);
                rs += s[nf][2 * rh] + s[nf][2 * rh + 1];
            }
            rs += __shfl_xor_sync(0xffffffffu, rs, 1);
            rs += __shfl_xor_sync(0xffffffffu, rs, 2);
            l_r[rh] = l_r[rh] * fac + rs;
            m_r[rh] = mnew;
#pragma unroll
            for (int nf = 0; nf < 8; nf++) {
                o[nf][2 * rh]     *= fac;
                o[nf][2 * rh + 1] *= fac;
            }
        }

        // ---- O += P V (P A-frags via in-register shfl relayout) ----
#pragma unroll
        for (int kc = 0; kc < 8; kc++) {
            const int src  = (gid << 2) | (tg >> 1);
            const int src2 = src + 2;
            float v0 = __shfl_sync(0xffffffffu, s[kc][0], src);
            float v1 = __shfl_sync(0xffffffffu, s[kc][1], src);
            float v2 = __shfl_sync(0xffffffffu, s[kc][2], src);
            float v3 = __shfl_sync(0xffffffffu, s[kc][3], src);
            float w0 = __shfl_sync(0xffffffffu, s[kc][0], src2);
            float w1 = __shfl_sync(0xffffffffu, s[kc][1], src2);
            float w2 = __shfl_sync(0xffffffffu, s[kc][2], src2);
            float w3 = __shfl_sync(0xffffffffu, s[kc][3], src2);
            const bool odd = tg & 1;
            uint32_t ap[4];
            ap[0] = f2tf32(odd ? v1 : v0);
            ap[1] = f2tf32(odd ? v3 : v2);
            ap[2] = f2tf32(odd ? w1 : w0);
            ap[3] = f2tf32(odd ? w3 : w2);

            const int kr = kc * 8 + tg;
#pragma unroll
            for (int nf = 0; nf < 8; nf++) {
                uint32_t bf[2];
                bf[0] = __float_as_uint(Vsm[kr * VST + nf * 8 + gid]);
                bf[1] = __float_as_uint(Vsm[(kr + 4) * VST + nf * 8 + gid]);
                mma_tf32(o[nf], ap, bf, o[nf]);
            }
        }

        // ---- finalize softmax pass at local/memory boundary and at end ----
        if (t == 15 || t == 16) {
#pragma unroll
            for (int rh = 0; rh < 2; rh++) {
                float inv = 1.0f / l_r[rh];
#pragma unroll
                for (int nf = 0; nf < 8; nf++) {
                    ofin[nf][2 * rh]     += o[nf][2 * rh] * inv;
                    ofin[nf][2 * rh + 1] += o[nf][2 * rh + 1] * inv;
                    o[nf][2 * rh] = 0.f;
                    o[nf][2 * rh + 1] = 0.f;
                }
                m_r[rh] = -1e30f;
                l_r[rh] = 0.f;
            }
        }
        __syncthreads();
    }

    // ---- write head-interleaved output, tf32-rounded (feeds out-proj MMA) ----
#pragma unroll
    for (int nf = 0; nf < 8; nf++) {
        int col = h * HDIM + nf * 8 + 2 * tg;
        size_t i0 = (size_t)(b * SEQ + qrow + gid) * EMB + col;
        size_t i1 = (size_t)(b * SEQ + qrow + gid + 8) * EMB + col;
        *reinterpret_cast<float2*>(&attn[i0]) =
            make_float2(rnd(ofin[nf][0]), rnd(ofin[nf][1]));
        *reinterpret_cast<float2*>(&attn[i1]) =
            make_float2(rnd(ofin[nf][2]), rnd(ofin[nf][3]));
    }
}

// ---------------------------------------------------------------------------
// Launch
// ---------------------------------------------------------------------------
extern "C" void kernel_launch(void* const* d_in, const int* in_sizes, int n_in,
                              void* d_out, int out_size)
{
    const float* x      = (const float*)d_in[0];
    const float* w_qkv  = (const float*)d_in[1];
    const float* b_qkv  = (const float*)d_in[2];
    const float* w_out  = (const float*)d_in[3];
    const float* b_out  = (const float*)d_in[4];
    const float* w_mem  = (const float*)d_in[5];
    const float* b_mem  = (const float*)d_in[6];
    const float* memory = (const float*)d_in[7];
    float* out = (float*)d_out;

    float *qkv, *attn, *xr, *memp, *mpart, *wqkvT, *woutT;
    cudaGetSymbolAddress((void**)&qkv,   g_qkv);
    cudaGetSymbolAddress((void**)&attn,  g_attn);
    cudaGetSymbolAddress((void**)&xr,    g_xr);
    cudaGetSymbolAddress((void**)&memp,  g_memproj);
    cudaGetSymbolAddress((void**)&mpart, g_mempart);
    cudaGetSymbolAddress((void**)&wqkvT, g_wqkvT);
    cudaGetSymbolAddress((void**)&woutT, g_woutT);

    cudaFuncSetAttribute(gemm_mma_kernel<true>,
                         cudaFuncAttributeMaxDynamicSharedMemorySize, GEMM_SMEM);
    cudaFuncSetAttribute(gemm_mma_kernel<false>,
                         cudaFuncAttributeMaxDynamicSharedMemorySize, GEMM_SMEM);
    cudaFuncSetAttribute(attn_mma_kernel,
                         cudaFuncAttributeMaxDynamicSharedMemorySize, ATTN_SMEM);

    // 0) producer-side tf32 rounding: weights (transposed) + x
    {
        dim3 blk(32, 8);
        transpose_kernel<<<dim3(QKVW / 32, EMB / 32), blk>>>(w_qkv, wqkvT, EMB, QKVW);
        transpose_kernel<<<dim3(EMB / 32, EMB / 32), blk>>>(w_out, woutT, EMB, EMB);
        round_kernel<<<(NTOK * EMB / 4 + 255) / 256, 256>>>(x, xr, NTOK * EMB / 4);
    }
    // 1) memory projection split-K + rounded reduce
    {
        memproj_splitk_kernel<<<dim3(EMB / 64, KSLICES), 256>>>(memory, w_mem, mpart);
        memproj_reduce_kernel<<<MEMSZ * EMB / (256 * 4), 256>>>(mpart, b_mem, memp);
    }
    // 2) QKV projection (rounded output -> attention)
    {
        dim3 grid(QKVW / 128, NTOK / 128);
        gemm_mma_kernel<true><<<grid, 256, GEMM_SMEM>>>(xr, wqkvT, b_qkv, qkv,
                                                        NTOK, QKVW, EMB);
    }
    // 3) fused local + memory attention
    {
        dim3 grid(SEQ / 128, BATCH * HEADS);
        attn_mma_kernel<<<grid, 256, ATTN_SMEM>>>(qkv, memp, attn);
    }
    // 4) output projection (final — NOT rounded)
    {
        dim3 grid(EMB / 128, NTOK / 128);
        gemm_mma_kernel<false><<<grid, 256, GEMM_SMEM>>>(attn, woutT, b_out, out,
                                                         NTOK, EMB, EMB);
    }
}

// round 11
// speedup vs baseline: 3.4690x; 1.0634x over previous
#include <cuda_runtime.h>
#include <cuda_bf16.h>
#include <cstdint>
#include <cstddef>

// ---------------------------------------------------------------------------
// InfiniAttention: B=8, T=1024, C=768, H=12, D=64, MEM=64
// tf32 mma.sync; fragment-packed GEMM operands (all LDS.128);
// memory-attention hoisted to its own kernel -> flash kernel runs 2 CTAs/SM.
// ---------------------------------------------------------------------------

#define BATCH 8
#define SEQ   1024
#define EMB   768
#define HEADS 12
#define HDIM  64
#define MEMSZ 64
#define NTOK  (BATCH * SEQ)       // 8192
#define QKVW  (3 * EMB)           // 2304
#define KSLICES 8                 // memproj split-K

// Scratch (device globals; no runtime allocation allowed)
__device__ float g_qkv[NTOK * QKVW];                // 75.5 MB (row-major, tf32)
__device__ float g_attn[NTOK * EMB];                // 25.2 MB (PACKED-A, tf32)
__device__ float g_xp[NTOK * EMB];                  // 25.2 MB (x, PACKED-A, tf32)
__device__ float g_omem[NTOK * EMB];                // 25.2 MB (mem-attn out, fp32)
__device__ float g_memproj[MEMSZ * EMB];            // 192 KB  (tf32)
__device__ float g_mempart[KSLICES * MEMSZ * EMB];  // 1.5 MB
__device__ float g_wqkvP[QKVW * EMB];               // 7.1 MB  (PACKED-B, tf32)
__device__ float g_woutP[EMB * EMB];                // 2.25 MB (PACKED-B, tf32)

// ===========================================================================
// Packed layouts (tile = 128 x 32, 4096 floats, contiguous 16 KB):
//  PA[mt][kt] slot ((mblk*4+kc)*32 + lane)*4 :
//    j0=(m=mblk*16+gid,      k=kc*8+tg)   j1=(m+8, k)
//    j2=(m,                  k+4)         j3=(m+8, k+4)
//  PB[nt][kt] slot ((nblk*2+kcp)*32 + lane)*4 :
//    j0=(n=nblk*8+gid, k=kcp*16+tg) j1=(k+4) j2=(k+8) j3=(k+12)
// ===========================================================================

__device__ __forceinline__ uint32_t smem_u32(const void* p) {
    uint32_t a;
    asm("{ .reg .u64 t; cvta.to.shared.u64 t, %1; cvt.u32.u64 %0, t; }"
        : "=r"(a) : "l"(p));
    return a;
}

__device__ __forceinline__ void mma_tf32(float d[4], const uint32_t a[4],
                                         const uint32_t b[2], const float c[4]) {
    asm volatile(
        "mma.sync.aligned.m16n8k8.row.col.f32.tf32.tf32.f32 "
        "{%0,%1,%2,%3}, {%4,%5,%6,%7}, {%8,%9}, {%10,%11,%12,%13};"
        : "=f"(d[0]), "=f"(d[1]), "=f"(d[2]), "=f"(d[3])
        : "r"(a[0]), "r"(a[1]), "r"(a[2]), "r"(a[3]),
          "r"(b[0]), "r"(b[1]),
          "f"(c[0]), "f"(c[1]), "f"(c[2]), "f"(c[3]));
}

__device__ __forceinline__ uint32_t f2tf32(float f) {
    uint32_t u;
    asm("cvt.rna.tf32.f32 %0, %1;" : "=r"(u) : "f"(f));
    return u;
}
__device__ __forceinline__ float rnd(float f) { return __uint_as_float(f2tf32(f)); }
__device__ __forceinline__ float4 rnd4(float4 v) {
    return make_float4(rnd(v.x), rnd(v.y), rnd(v.z), rnd(v.w));
}

#define CP_ASYNC16(dst_u32, src_ptr) \
    asm volatile("cp.async.cg.shared.global [%0], [%1], 16;" \
                 :: "r"(dst_u32), "l"(src_ptr) : "memory")
#define CP_COMMIT() asm volatile("cp.async.commit_group;" ::: "memory")
#define CP_WAIT0()  asm volatile("cp.async.wait_group 0;" ::: "memory")
#define CP_WAIT1()  asm volatile("cp.async.wait_group 1;" ::: "memory")

// ===========================================================================
// pack_a: row-major [M][K] -> PA tiles, tf32-rounded. grid (K/32, M/128).
// ===========================================================================
__global__ __launch_bounds__(256) void pack_a_kernel(
    const float* __restrict__ src, float* __restrict__ dst, int K)
{
    __shared__ float ts[128][36];
    const int tid = threadIdx.x;
    const int kt = blockIdx.x, mt = blockIdx.y;
    const int KT = K >> 5;

#pragma unroll
    for (int i = 0; i < 4; i++) {
        int idx = tid + i * 256;            // 0..1023 float4s
        int r = idx >> 3, c4 = (idx & 7) * 4;
        float4 v = *reinterpret_cast<const float4*>(
            &src[(size_t)(mt * 128 + r) * K + kt * 32 + c4]);
        *reinterpret_cast<float4*>(&ts[r][c4]) = rnd4(v);
    }
    __syncthreads();

    float* base = &dst[((size_t)mt * KT + kt) * 4096];
#pragma unroll
    for (int i = 0; i < 4; i++) {
        int slot = tid + i * 256;
        int lane = slot & 31, kc = (slot >> 5) & 3, mblk = slot >> 7;
        int gid = lane >> 2, tg = lane & 3;
        int m = mblk * 16 + gid, k = kc * 8 + tg;
        float4 v = make_float4(ts[m][k], ts[m + 8][k], ts[m][k + 4], ts[m + 8][k + 4]);
        *reinterpret_cast<float4*>(&base[slot * 4]) = v;
    }
}

// ===========================================================================
// pack_b: W row-major [K][N] (BT[n][k] = W[k][n]) -> PB tiles, tf32-rounded.
// grid (K/32, N/128).
// ===========================================================================
__global__ __launch_bounds__(256) void pack_b_kernel(
    const float* __restrict__ W, float* __restrict__ dst, int K, int N)
{
    __shared__ float tw[32][132];
    const int tid = threadIdx.x;
    const int kt = blockIdx.x, nt = blockIdx.y;
    const int KT = K >> 5;

#pragma unroll
    for (int i = 0; i < 4; i++) {
        int idx = tid + i * 256;
        int r = idx >> 5, c4 = (idx & 31) * 4;
        float4 v = *reinterpret_cast<const float4*>(
            &W[(size_t)(kt * 32 + r) * N + nt * 128 + c4]);
        *reinterpret_cast<float4*>(&tw[r][c4]) = rnd4(v);
    }
    __syncthreads();

    float* base = &dst[((size_t)nt * KT + kt) * 4096];
#pragma unroll
    for (int i = 0; i < 4; i++) {
        int slot = tid + i * 256;
        int lane = slot & 31, kcp = (slot >> 5) & 1, nblk = slot >> 6;
        int gid = lane >> 2, tg = lane & 3;
        int n = nblk * 8 + gid, k = kcp * 16 + tg;
        float4 v = make_float4(tw[k][n], tw[k + 4][n], tw[k + 8][n], tw[k + 12][n]);
        *reinterpret_cast<float4*>(&base[slot * 4]) = v;
    }
}

// ===========================================================================
// tf32 MMA GEMM + bias, packed A & B, 3-stage cp.async.
// C[M,N] = A @ B^T + bias, C row-major. 128x128x32 tile, 256 threads.
// Smem: 3 x (16KB A + 16KB B) = 98304 B.
// ===========================================================================
#define GEMM_SMEM 98304

template<bool RND_OUT>
__global__ __launch_bounds__(256, 2) void gemm_mma_kernel(
    const float* __restrict__ PA, const float* __restrict__ PB,
    const float* __restrict__ bias, float* __restrict__ C,
    int M, int N, int K)
{
    extern __shared__ __align__(16) float sm[];
    const uint32_t sb = smem_u32(sm);

    const int tid  = threadIdx.x;
    const int lane = tid & 31;
    const int warp = tid >> 5;
    const int gid  = lane >> 2;
    const int tg   = lane & 3;
    const int mblkb = (warp & 3) * 2;     // A mblk base (2 per warp)
    const int nblkb = (warp >> 2) * 8;    // B nblk base (8 per warp)
    const int row0 = blockIdx.y * 128;
    const int col0 = blockIdx.x * 128;
    const int KT   = K >> 5;

    float acc[2][8][4];
#pragma unroll
    for (int i = 0; i < 2; i++)
#pragma unroll
        for (int j = 0; j < 8; j++)
#pragma unroll
            for (int e = 0; e < 4; e++) acc[i][j][e] = 0.f;

    const float* abase = &PA[(size_t)blockIdx.y * KT * 4096];
    const float* bbase = &PB[(size_t)blockIdx.x * KT * 4096];

    auto stage = [&](int kt) {
        const int s = kt % 3;
        const uint32_t ab = sb + s * 32768u;
        const uint32_t bb = ab + 16384u;
        const float* as = abase + (size_t)kt * 4096;
        const float* bs = bbase + (size_t)kt * 4096;
#pragma unroll
        for (int i = 0; i < 4; i++) {
            int c = tid + i * 256;
            CP_ASYNC16(ab + c * 16, as + c * 4);
            CP_ASYNC16(bb + c * 16, bs + c * 4);
        }
        CP_COMMIT();
    };

    stage(0);
    stage(1);

    for (int kt = 0; kt < KT; kt++) {
        if (kt == KT - 1) { CP_WAIT0(); } else { CP_WAIT1(); }
        __syncthreads();

        const float* As = sm + (kt % 3) * 8192;
        const float* Bs = As + 4096;

#pragma unroll
        for (int kcp = 0; kcp < 2; kcp++) {
            float4 bq[8];
#pragma unroll
            for (int nf = 0; nf < 8; nf++)
                bq[nf] = *reinterpret_cast<const float4*>(
                    &Bs[((nblkb + nf) * 2 + kcp) * 128 + lane * 4]);
            float4 a4[2][2];
#pragma unroll
            for (int mf = 0; mf < 2; mf++)
#pragma unroll
                for (int h = 0; h < 2; h++)
                    a4[mf][h] = *reinterpret_cast<const float4*>(
                        &As[((mblkb + mf) * 4 + kcp * 2 + h) * 128 + lane * 4]);
#pragma unroll
            for (int h = 0; h < 2; h++) {
#pragma unroll
                for (int mf = 0; mf < 2; mf++) {
                    uint32_t af[4] = {
                        __float_as_uint(a4[mf][h].x), __float_as_uint(a4[mf][h].y),
                        __float_as_uint(a4[mf][h].z), __float_as_uint(a4[mf][h].w)};
#pragma unroll
                    for (int nf = 0; nf < 8; nf++) {
                        uint32_t bf[2];
                        bf[0] = __float_as_uint(h ? bq[nf].z : bq[nf].x);
                        bf[1] = __float_as_uint(h ? bq[nf].w : bq[nf].y);
                        mma_tf32(acc[mf][nf], af, bf, acc[mf][nf]);
                    }
                }
            }
        }

        if (kt + 2 < KT) stage(kt + 2);
    }

#pragma unroll
    for (int mf = 0; mf < 2; mf++) {
#pragma unroll
        for (int nf = 0; nf < 8; nf++) {
            int row = row0 + (mblkb + mf) * 16 + gid;
            int col = col0 + nblkb * 8 + nf * 8 + 2 * tg;
            float2 bz = *reinterpret_cast<const float2*>(&bias[col]);
            float2 r0v = make_float2(acc[mf][nf][0] + bz.x, acc[mf][nf][1] + bz.y);
            float2 r1v = make_float2(acc[mf][nf][2] + bz.x, acc[mf][nf][3] + bz.y);
            if (RND_OUT) {
                r0v.x = rnd(r0v.x); r0v.y = rnd(r0v.y);
                r1v.x = rnd(r1v.x); r1v.y = rnd(r1v.y);
            }
            *reinterpret_cast<float2*>(&C[(size_t)row * N + col]) = r0v;
            *reinterpret_cast<float2*>(&C[(size_t)(row + 8) * N + col]) = r1v;
        }
    }
}

// ===========================================================================
// Memory projection, split-K SIMT + rounded reduce.
// ===========================================================================
__global__ __launch_bounds__(256) void memproj_splitk_kernel(
    const float* __restrict__ mem, const float* __restrict__ w,
    float* __restrict__ part)
{
    __shared__ float As[16][64];
    __shared__ float Bs[16][68];

    const int tid = threadIdx.x;
    const int tx  = tid & 15;
    const int ty  = tid >> 4;
    const int kbase = blockIdx.y * 96;
    const int col0  = blockIdx.x * 64;

    float acc[4][4];
#pragma unroll
    for (int i = 0; i < 4; i++)
#pragma unroll
        for (int j = 0; j < 4; j++) acc[i][j] = 0.f;

    for (int k0 = 0; k0 < 96; k0 += 16) {
        {
            int f  = tid * 4;
            int r  = f >> 4;
            int c4 = f & 15;
            float4 v = *reinterpret_cast<const float4*>(
                &mem[(size_t)r * EMB + kbase + k0 + c4]);
            As[c4 + 0][r] = v.x; As[c4 + 1][r] = v.y;
            As[c4 + 2][r] = v.z; As[c4 + 3][r] = v.w;
        }
        {
            int f  = tid * 4;
            int r  = f >> 6;
            int c4 = f & 63;
            *reinterpret_cast<float4*>(&Bs[r][c4]) =
                *reinterpret_cast<const float4*>(
                    &w[(size_t)(kbase + k0 + r) * EMB + col0 + c4]);
        }
        __syncthreads();
#pragma unroll
        for (int kk = 0; kk < 16; kk++) {
            float a[4], b[4];
#pragma unroll
            for (int i = 0; i < 4; i++) a[i] = As[kk][ty * 4 + i];
#pragma unroll
            for (int j = 0; j < 4; j++) b[j] = Bs[kk][tx * 4 + j];
#pragma unroll
            for (int i = 0; i < 4; i++)
#pragma unroll
                for (int j = 0; j < 4; j++)
                    acc[i][j] = fmaf(a[i], b[j], acc[i][j]);
        }
        __syncthreads();
    }

#pragma unroll
    for (int i = 0; i < 4; i++) {
        int row = ty * 4 + i;
        *reinterpret_cast<float4*>(
            &part[(size_t)(blockIdx.y * MEMSZ + row) * EMB + col0 + tx * 4]) =
            make_float4(acc[i][0], acc[i][1], acc[i][2], acc[i][3]);
    }
}

__global__ __launch_bounds__(256) void memproj_reduce_kernel(
    const float* __restrict__ part, const float* __restrict__ bias,
    float* __restrict__ outp)
{
    int i4 = (blockIdx.x * 256 + threadIdx.x) * 4;
    int col = i4 % EMB;
    float4 s = *reinterpret_cast<const float4*>(&bias[col]);
#pragma unroll
    for (int sl = 0; sl < KSLICES; sl++) {
        float4 p = *reinterpret_cast<const float4*>(&part[(size_t)sl * MEMSZ * EMB + i4]);
        s.x += p.x; s.y += p.y; s.z += p.z; s.w += p.w;
    }
    *reinterpret_cast<float4*>(&outp[i4]) = rnd4(s);
}

// ===========================================================================
// Memory attention: o_mem = softmax(Q Mk^T / 8) Mk, per (128-token tile, head).
// Single 64-key tile, exact softmax, output row-major fp32. grid (64, 12).
// ===========================================================================
__global__ __launch_bounds__(256) void memattn_kernel(
    const float* __restrict__ qkv, const float* __restrict__ memproj,
    float* __restrict__ omem)
{
    __shared__ float Km[64][68];

    const int tid  = threadIdx.x;
    const int warp = tid >> 5;
    const int lane = tid & 31;
    const int gid  = lane >> 2;
    const int tg   = lane & 3;
    const int h    = blockIdx.y;
    const int trow = blockIdx.x * 128 + warp * 16;

    // load head slice of projected memory (K = V)
#pragma unroll
    for (int i = 0; i < 4; i++) {
        int idx = tid + i * 256;
        int r = idx >> 4, d4 = (idx & 15) * 4;
        *reinterpret_cast<float4*>(&Km[r][d4]) =
            *reinterpret_cast<const float4*>(&memproj[(size_t)r * EMB + h * HDIM + d4]);
    }

    // Q fragments, 1/8 scale folded
    uint32_t aq[8][4];
    {
        const float* qb = &qkv[(size_t)trow * QKVW + h * HDIM];
#pragma unroll
        for (int kc = 0; kc < 8; kc++) {
            int k = kc * 8 + tg;
            aq[kc][0] = __float_as_uint(qb[(size_t)gid * QKVW + k] * 0.125f);
            aq[kc][1] = __float_as_uint(qb[(size_t)(gid + 8) * QKVW + k] * 0.125f);
            aq[kc][2] = __float_as_uint(qb[(size_t)gid * QKVW + k + 4] * 0.125f);
            aq[kc][3] = __float_as_uint(qb[(size_t)(gid + 8) * QKVW + k + 4] * 0.125f);
        }
    }
    __syncthreads();

    // S = (Q/8) Mk^T
    float s[8][4];
#pragma unroll
    for (int nf = 0; nf < 8; nf++)
#pragma unroll
        for (int e = 0; e < 4; e++) s[nf][e] = 0.f;
#pragma unroll
    for (int nf = 0; nf < 8; nf++) {
        const int krow = nf * 8 + gid;
#pragma unroll
        for (int kc = 0; kc < 8; kc++) {
            uint32_t bf[2];
            bf[0] = __float_as_uint(Km[krow][kc * 8 + tg]);
            bf[1] = __float_as_uint(Km[krow][kc * 8 + tg + 4]);
            mma_tf32(s[nf], aq[kc], bf, s[nf]);
        }
    }

    // exact softmax over the 64 keys
    float linv[2];
#pragma unroll
    for (int rh = 0; rh < 2; rh++) {
        float rm = -1e30f;
#pragma unroll
        for (int nf = 0; nf < 8; nf++)
            rm = fmaxf(rm, fmaxf(s[nf][2 * rh], s[nf][2 * rh + 1]));
        rm = fmaxf(rm, __shfl_xor_sync(0xffffffffu, rm, 1));
        rm = fmaxf(rm, __shfl_xor_sync(0xffffffffu, rm, 2));
        float rs = 0.f;
#pragma unroll
        for (int nf = 0; nf < 8; nf++) {
            s[nf][2 * rh]     = __expf(s[nf][2 * rh] - rm);
            s[nf][2 * rh + 1] = __expf(s[nf][2 * rh + 1] - rm);
            rs += s[nf][2 * rh] + s[nf][2 * rh + 1];
        }
        rs += __shfl_xor_sync(0xffffffffu, rs, 1);
        rs += __shfl_xor_sync(0xffffffffu, rs, 2);
        linv[rh] = 1.0f / rs;
    }

    // O = P Mk
    float o[8][4];
#pragma unroll
    for (int nf = 0; nf < 8; nf++)
#pragma unroll
        for (int e = 0; e < 4; e++) o[nf][e] = 0.f;
#pragma unroll
    for (int kc = 0; kc < 8; kc++) {
        const int src  = (gid << 2) | (tg >> 1);
        const int src2 = src + 2;
        float v0 = __shfl_sync(0xffffffffu, s[kc][0], src);
        float v1 = __shfl_sync(0xffffffffu, s[kc][1], src);
        float v2 = __shfl_sync(0xffffffffu, s[kc][2], src);
        float v3 = __shfl_sync(0xffffffffu, s[kc][3], src);
        float w0 = __shfl_sync(0xffffffffu, s[kc][0], src2);
        float w1 = __shfl_sync(0xffffffffu, s[kc][1], src2);
        float w2 = __shfl_sync(0xffffffffu, s[kc][2], src2);
        float w3 = __shfl_sync(0xffffffffu, s[kc][3], src2);
        const bool odd = tg & 1;
        uint32_t ap[4];
        ap[0] = f2tf32(odd ? v1 : v0);
        ap[1] = f2tf32(odd ? v3 : v2);
        ap[2] = f2tf32(odd ? w1 : w0);
        ap[3] = f2tf32(odd ? w3 : w2);
        const int kr = kc * 8 + tg;
#pragma unroll
        for (int nf = 0; nf < 8; nf++) {
            uint32_t bf[2];
            bf[0] = __float_as_uint(Km[kr][nf * 8 + gid]);
            bf[1] = __float_as_uint(Km[kr + 4][nf * 8 + gid]);
            mma_tf32(o[nf], ap, bf, o[nf]);
        }
    }

    // write normalized output, row-major fp32
#pragma unroll
    for (int nf = 0; nf < 8; nf++) {
        int col = h * HDIM + nf * 8 + 2 * tg;
        size_t i0 = (size_t)(trow + gid) * EMB + col;
        size_t i1 = (size_t)(trow + gid + 8) * EMB + col;
        *reinterpret_cast<float2*>(&omem[i0]) =
            make_float2(o[nf][0] * linv[0], o[nf][1] * linv[0]);
        *reinterpret_cast<float2*>(&omem[i1]) =
            make_float2(o[nf][2] * linv[1], o[nf][3] * linv[1]);
    }
}

// ===========================================================================
// Fused local flash attention (16 tiles), tf32 MMA, cp.async double-buffered.
// Epilogue adds o_mem and writes g_attn in PACKED-A layout (tf32-rounded).
// CTA = (b,h) x 128 queries; 256 threads; 2 CTAs/SM.
// ===========================================================================
#define KST 76
#define VST 72
#define ATTN_SMEM 75776

__global__ __launch_bounds__(256, 2) void attn_mma_kernel(
    const float* __restrict__ qkv, const float* __restrict__ omem,
    float* __restrict__ attnP)
{
    extern __shared__ __align__(16) float sm[];
    const uint32_t sb = smem_u32(sm);

    const int tid  = threadIdx.x;
    const int warp = tid >> 5;
    const int lane = tid & 31;
    const int gid  = lane >> 2;
    const int tg   = lane & 3;
    const int b    = blockIdx.y / HEADS;
    const int h    = blockIdx.y % HEADS;
    const int qrow = blockIdx.x * 128 + warp * 16;

    // Q fragments, 1/8 scale folded
    uint32_t aq[8][4];
    {
        const float* qb = &qkv[(size_t)(b * SEQ + qrow) * QKVW + h * HDIM];
#pragma unroll
        for (int kc = 0; kc < 8; kc++) {
            int k = kc * 8 + tg;
            aq[kc][0] = __float_as_uint(qb[(size_t)gid * QKVW + k] * 0.125f);
            aq[kc][1] = __float_as_uint(qb[(size_t)(gid + 8) * QKVW + k] * 0.125f);
            aq[kc][2] = __float_as_uint(qb[(size_t)gid * QKVW + k + 4] * 0.125f);
            aq[kc][3] = __float_as_uint(qb[(size_t)(gid + 8) * QKVW + k + 4] * 0.125f);
        }
    }

    float o[8][4], m_r[2], l_r[2];
#pragma unroll
    for (int nf = 0; nf < 8; nf++)
#pragma unroll
        for (int e = 0; e < 4; e++) o[nf][e] = 0.f;
    m_r[0] = m_r[1] = -1e30f;
    l_r[0] = l_r[1] = 0.f;

    auto stage = [&](int t, int s) {
        const uint32_t kb = sb + s * 37888u;
        const uint32_t vb = kb + 19456u;
#pragma unroll
        for (int i = 0; i < 4; i++) {
            int idx = tid + i * 256;
            int r   = idx >> 4;
            int c4  = (idx & 15) * 4;
            size_t base = (size_t)(b * SEQ + t * 64 + r) * QKVW + h * HDIM + c4;
            CP_ASYNC16(kb + (r * KST + c4) * 4, &qkv[base + EMB]);
            CP_ASYNC16(vb + (r * VST + c4) * 4, &qkv[base + 2 * EMB]);
        }
        CP_COMMIT();
    };

    stage(0, 0);

    for (int t = 0; t < 16; t++) {
        CP_WAIT0();
        __syncthreads();
        if (t + 1 < 16) stage(t + 1, (t + 1) & 1);

        const float* Ksm = sm + (t & 1) * 9472;
        const float* Vsm = Ksm + 4864;

        // ---- S = (Q/8) K^T ----
        float s[8][4];
#pragma unroll
        for (int nf = 0; nf < 8; nf++)
#pragma unroll
            for (int e = 0; e < 4; e++) s[nf][e] = 0.f;

#pragma unroll
        for (int nf = 0; nf < 8; nf++) {
            const int krow = nf * 8 + gid;
#pragma unroll
            for (int kc = 0; kc < 8; kc++) {
                uint32_t bf[2];
                bf[0] = __float_as_uint(Ksm[krow * KST + kc * 8 + tg]);
                bf[1] = __float_as_uint(Ksm[krow * KST + kc * 8 + tg + 4]);
                mma_tf32(s[nf], aq[kc], bf, s[nf]);
            }
        }

        // ---- online softmax ----
#pragma unroll
        for (int rh = 0; rh < 2; rh++) {
            float rm = -1e30f;
#pragma unroll
            for (int nf = 0; nf < 8; nf++)
                rm = fmaxf(rm, fmaxf(s[nf][2 * rh], s[nf][2 * rh + 1]));
            rm = fmaxf(rm, __shfl_xor_sync(0xffffffffu, rm, 1));
            rm = fmaxf(rm, __shfl_xor_sync(0xffffffffu, rm, 2));
            float mnew = fmaxf(m_r[rh], rm);
            float fac  = __expf(m_r[rh] - mnew);
            float rs   = 0.f;
#pragma unroll
            for (int nf = 0; nf < 8; nf++) {
                s[nf][2 * rh]     = __expf(s[nf][2 * rh] - mnew);
                s[nf][2 * rh + 1] = __expf(s[nf][2 * rh + 1] - mnew);
                rs += s[nf][2 * rh] + s[nf][2 * rh + 1];
            }
            rs += __shfl_xor_sync(0xffffffffu, rs, 1);
            rs += __shfl_xor_sync(0xffffffffu, rs, 2);
            l_r[rh] = l_r[rh] * fac + rs;
            m_r[rh] = mnew;
#pragma unroll
            for (int nf = 0; nf < 8; nf++) {
                o[nf][2 * rh]     *= fac;
                o[nf][2 * rh + 1] *= fac;
            }
        }

        // ---- O += P V ----
#pragma unroll
        for (int kc = 0; kc < 8; kc++) {
            const int src  = (gid << 2) | (tg >> 1);
            const int src2 = src + 2;
            float v0 = __shfl_sync(0xffffffffu, s[kc][0], src);
            float v1 = __shfl_sync(0xffffffffu, s[kc][1], src);
            float v2 = __shfl_sync(0xffffffffu, s[kc][2], src);
            float v3 = __shfl_sync(0xffffffffu, s[kc][3], src);
            float w0 = __shfl_sync(0xffffffffu, s[kc][0], src2);
            float w1 = __shfl_sync(0xffffffffu, s[kc][1], src2);
            float w2 = __shfl_sync(0xffffffffu, s[kc][2], src2);
            float w3 = __shfl_sync(0xffffffffu, s[kc][3], src2);
            const bool odd = tg & 1;
            uint32_t ap[4];
            ap[0] = f2tf32(odd ? v1 : v0);
            ap[1] = f2tf32(odd ? v3 : v2);
            ap[2] = f2tf32(odd ? w1 : w0);
            ap[3] = f2tf32(odd ? w3 : w2);

            const int kr = kc * 8 + tg;
#pragma unroll
            for (int nf = 0; nf < 8; nf++) {
                uint32_t bf[2];
                bf[0] = __float_as_uint(Vsm[kr * VST + nf * 8 + gid]);
                bf[1] = __float_as_uint(Vsm[(kr + 4) * VST + nf * 8 + gid]);
                mma_tf32(o[nf], ap, bf, o[nf]);
            }
        }
    }

    // ---- epilogue: normalize, add o_mem, write PACKED-A tf32 ----
    const float inv0 = 1.0f / l_r[0];
    const float inv1 = 1.0f / l_r[1];
    const int mt = blockIdx.x;            // 128-token tile
    const int mblk = warp;
    const int KT = EMB / 32;              // 24
    const int tok = b * SEQ + qrow;       // global token of row gid==0

#pragma unroll
    for (int nf = 0; nf < 8; nf++) {
        int col = h * HDIM + nf * 8 + 2 * tg;
        size_t i0 = (size_t)(tok + gid) * EMB + col;
        size_t i1 = (size_t)(tok + gid + 8) * EMB + col;
        float2 me0 = *reinterpret_cast<const float2*>(&omem[i0]);
        float2 me1 = *reinterpret_cast<const float2*>(&omem[i1]);
        float e0 = o[nf][0] * inv0 + me0.x;   // (row gid,   col)
        float e1 = o[nf][1] * inv0 + me0.y;   // (row gid,   col+1)
        float e2 = o[nf][2] * inv1 + me1.x;   // (row gid+8, col)
        float e3 = o[nf][3] * inv1 + me1.y;   // (row gid+8, col+1)

        // packed-A address: tile (b*8 + mt, kt), kc = nf%4
        int kt = h * 2 + (nf >> 2);
        int kc = nf & 3;
        float* base = &attnP[(((size_t)(b * 8 + mt)) * KT + kt) * 4096
                             + (mblk * 4 + kc) * 128];
        int jlow  = (tg < 2) ? 0 : 2;
        int laneA = gid * 4 + ((2 * tg) & 3);
        int laneB = gid * 4 + ((2 * tg + 1) & 3);
        *reinterpret_cast<float2*>(&base[laneA * 4 + jlow]) =
            make_float2(rnd(e0), rnd(e2));
        *reinterpret_cast<float2*>(&base[laneB * 4 + jlow]) =
            make_float2(rnd(e1), rnd(e3));
    }
}

// ---------------------------------------------------------------------------
// Launch
// ---------------------------------------------------------------------------
extern "C" void kernel_launch(void* const* d_in, const int* in_sizes, int n_in,
                              void* d_out, int out_size)
{
    const float* x      = (const float*)d_in[0];
    const float* w_qkv  = (const float*)d_in[1];
    const float* b_qkv  = (const float*)d_in[2];
    const float* w_out  = (const float*)d_in[3];
    const float* b_out  = (const float*)d_in[4];
    const float* w_mem  = (const float*)d_in[5];
    const float* b_mem  = (const float*)d_in[6];
    const float* memory = (const float*)d_in[7];
    float* out = (float*)d_out;

    float *qkv, *attnP, *xp, *omem, *memp, *mpart, *wqkvP, *woutP;
    cudaGetSymbolAddress((void**)&qkv,   g_qkv);
    cudaGetSymbolAddress((void**)&attnP, g_attn);
    cudaGetSymbolAddress((void**)&xp,    g_xp);
    cudaGetSymbolAddress((void**)&omem,  g_omem);
    cudaGetSymbolAddress((void**)&memp,  g_memproj);
    cudaGetSymbolAddress((void**)&mpart, g_mempart);
    cudaGetSymbolAddress((void**)&wqkvP, g_wqkvP);
    cudaGetSymbolAddress((void**)&woutP, g_woutP);

    cudaFuncSetAttribute(gemm_mma_kernel<true>,
                         cudaFuncAttributeMaxDynamicSharedMemorySize, GEMM_SMEM);
    cudaFuncSetAttribute(gemm_mma_kernel<false>,
                         cudaFuncAttributeMaxDynamicSharedMemorySize, GEMM_SMEM);
    cudaFuncSetAttribute(attn_mma_kernel,
                         cudaFuncAttributeMaxDynamicSharedMemorySize, ATTN_SMEM);

    // 0) operand packing (tf32-rounded): x -> PA, weights -> PB
    pack_a_kernel<<<dim3(EMB / 32, NTOK / 128), 256>>>(x, xp, EMB);
    pack_b_kernel<<<dim3(EMB / 32, QKVW / 128), 256>>>(w_qkv, wqkvP, EMB, QKVW);
    pack_b_kernel<<<dim3(EMB / 32, EMB / 128), 256>>>(w_out, woutP, EMB, EMB);

    // 1) memory projection split-K + rounded reduce
    memproj_splitk_kernel<<<dim3(EMB / 64, KSLICES), 256>>>(memory, w_mem, mpart);
    memproj_reduce_kernel<<<MEMSZ * EMB / (256 * 4), 256>>>(mpart, b_mem, memp);

    // 2) QKV projection (packed A/B, rounded row-major output)
    {
        dim3 grid(QKVW / 128, NTOK / 128);
        gemm_mma_kernel<true><<<grid, 256, GEMM_SMEM>>>(xp, wqkvP, b_qkv, qkv,
                                                        NTOK, QKVW, EMB);
    }
    // 3) memory attention (exact softmax over 64 keys)
    memattn_kernel<<<dim3(NTOK / 128, HEADS), 256>>>(qkv, memp, omem);

    // 4) local flash attention + o_mem add, packed-A output
    {
        dim3 grid(SEQ / 128, BATCH * HEADS);
        attn_mma_kernel<<<grid, 256, ATTN_SMEM>>>(qkv, omem, attnP);
    }
    // 5) output projection (packed A/B, final fp32 output)
    {
        dim3 grid(EMB / 128, NTOK / 128);
        gemm_mma_kernel<false><<<grid, 256, GEMM_SMEM>>>(attnP, woutP, b_out, out,
                                                         NTOK, EMB, EMB);
    }
}